// round 5
// baseline (speedup 1.0000x reference)
#include <cuda_runtime.h>
#include <cstdint>

#define N_TOK   2048
#define DIM     256
#define KMEM    65536
#define KSHORT  64
#define VOCAB   50257
#define RHO_C   1.0f
#define TAU_C   0.1f
#define ETA_C   0.1f

// ---------------- scratch (static __device__ — no allocation) ----------------
__device__ float g_S[(size_t)N_TOK * KMEM];   // 512 MB scores
__device__ float g_E[N_TOK * DIM];
__device__ float g_X[N_TOK * DIM];
__device__ float g_Y[N_TOK * DIM];
__device__ float g_bsum[8 * DIM];
__device__ int   g_K[N_TOK * KSHORT];

// TF32 rounding (kept for the fallback branch; unused when TF32=0)
__device__ __forceinline__ float tf32r(float x) {
    float r;
    asm("cvt.rna.tf32.f32 %0, %1;" : "=f"(r) : "f"(x));
    return r;
}

// ---------------- embed gather ----------------
__global__ void k_embed(const int* __restrict__ tok, const float* __restrict__ tab,
                        float* __restrict__ E) {
    int t = blockIdx.x, c = threadIdx.x;
    E[t * DIM + c] = tab[(size_t)tok[t] * DIM + c];
}

// ---------------- causal cumulative mean (2-phase) ----------------
__global__ void k_colsum(const float* __restrict__ E, float* __restrict__ bs) {
    int b = blockIdx.x, j = threadIdx.x;
    float s = 0.f;
    int base = b * 256;
#pragma unroll 4
    for (int r = 0; r < 256; r++) s += E[(base + r) * DIM + j];
    bs[b * DIM + j] = s;
}

__global__ void k_cummean(const float* __restrict__ E, const float* __restrict__ bs,
                          float* __restrict__ X) {
    int b = blockIdx.x, j = threadIdx.x;
    float acc = 0.f;
    for (int p = 0; p < b; p++) acc += bs[p * DIM + j];
    int base = b * 256;
    for (int r = 0; r < 256; r++) {
        int t = base + r;
        acc += E[t * DIM + j];
        X[t * DIM + j] = acc / (float)(t + 1);
    }
}

// ---------------- GEMM: C[t][m] = dot(Am[t], Bm[m]), K=256 ----------------
template <int TF32>
__global__ __launch_bounds__(256) void k_gemm(const float* __restrict__ Am,
                                              const float* __restrict__ Bm,
                                              float* __restrict__ C,
                                              int ncols, int guard) {
    __shared__ __align__(16) float Es[32][68];
    __shared__ float Bs[256][33];
    int tid = threadIdx.x;
    int tx = tid & 31, ty = tid >> 5;
    int mBase = blockIdx.x * 256;
    int tBase = blockIdx.y * 64;

    float acc[8][8];
#pragma unroll
    for (int i = 0; i < 8; i++)
#pragma unroll
        for (int j = 0; j < 8; j++) acc[i][j] = 0.f;

    for (int kc = 0; kc < 256; kc += 32) {
#pragma unroll
        for (int l = 0; l < 2; l++) {
            int f = tid + l * 256;
            int t = f >> 3, k4 = f & 7;
            float4 v = *(const float4*)&Am[(size_t)(tBase + t) * DIM + kc + k4 * 4];
            if (TF32) { v.x = tf32r(v.x); v.y = tf32r(v.y); v.z = tf32r(v.z); v.w = tf32r(v.w); }
            Es[k4 * 4 + 0][t] = v.x; Es[k4 * 4 + 1][t] = v.y;
            Es[k4 * 4 + 2][t] = v.z; Es[k4 * 4 + 3][t] = v.w;
        }
#pragma unroll
        for (int l = 0; l < 8; l++) {
            int f = tid + l * 256;
            int r = f >> 3, k4 = f & 7;
            float4 v = *(const float4*)&Bm[(size_t)(mBase + r) * DIM + kc + k4 * 4];
            if (TF32) { v.x = tf32r(v.x); v.y = tf32r(v.y); v.z = tf32r(v.z); v.w = tf32r(v.w); }
            float* d = &Bs[r][k4 * 4];
            d[0] = v.x; d[1] = v.y; d[2] = v.z; d[3] = v.w;
        }
        __syncthreads();
#pragma unroll 4
        for (int k = 0; k < 32; k++) {
            float4 e0 = *(const float4*)&Es[k][ty * 8];
            float4 e1 = *(const float4*)&Es[k][ty * 8 + 4];
            float e[8] = {e0.x, e0.y, e0.z, e0.w, e1.x, e1.y, e1.z, e1.w};
            float mv[8];
#pragma unroll
            for (int j = 0; j < 8; j++) mv[j] = Bs[tx + 32 * j][k];
#pragma unroll
            for (int i = 0; i < 8; i++)
#pragma unroll
                for (int j = 0; j < 8; j++)
                    acc[i][j] = fmaf(e[i], mv[j], acc[i][j]);
        }
        __syncthreads();
    }
#pragma unroll
    for (int i = 0; i < 8; i++) {
        int t = tBase + ty * 8 + i;
        size_t row = (size_t)t * (size_t)ncols;
#pragma unroll
        for (int j = 0; j < 8; j++) {
            int m = mBase + tx + 32 * j;
            if (!guard || m < ncols) C[row + m] = acc[i][j];
        }
    }
}

// ---------------- exact top-64: single-shot strip-max threshold ----------------
__device__ __forceinline__ unsigned int ordf(float f) {
    unsigned int u = __float_as_uint(f);
    return (u & 0x80000000u) ? ~u : (u | 0x80000000u);
}

__device__ __forceinline__ unsigned long long mk_key(float v, int idx) {
    return ((unsigned long long)ordf(v) << 32) | (unsigned int)(65535 - idx);
}

__global__ __launch_bounds__(256) void k_topk2(const float* __restrict__ S,
                                               int* __restrict__ Kset) {
    __shared__ unsigned long long cand[2048];
    __shared__ unsigned long long tmax[256];
    __shared__ int cnt;
    int tid = threadIdx.x;
    int t = blockIdx.x;
    const float* row = S + (size_t)t * KMEM;

    // pass 1: per-thread strip max (strided, coalesced)
    unsigned long long mk = 0ull;
#pragma unroll 8
    for (int i = 0; i < 256; i++) {
        int idx = tid + (i << 8);
        unsigned long long key = mk_key(row[idx], idx);
        if (key > mk) mk = key;
    }
    tmax[tid] = mk;
    if (tid == 0) cnt = 0;
    __syncthreads();

    // bitonic sort 256 strip maxima, descending (1 elem/thread)
    for (int k = 2; k <= 256; k <<= 1) {
        for (int j = k >> 1; j > 0; j >>= 1) {
            int ix = tid ^ j;
            if (ix > tid) {
                unsigned long long a = tmax[tid], b = tmax[ix];
                bool up = ((tid & k) == 0);
                if (up ? (a < b) : (a > b)) { tmax[tid] = b; tmax[ix] = a; }
            }
            __syncthreads();
        }
    }
    // tau = 64th-largest strip max. 64 strips each contain a key >= tau,
    // so the row's 64th-largest key >= tau => top-64 subset of {key >= tau}.
    unsigned long long tau = tmax[63];
    __syncthreads();

    // pass 2: collect all keys >= tau (expected ~100, capacity 2048)
#pragma unroll 4
    for (int i = 0; i < 256; i++) {
        int idx = tid + (i << 8);
        unsigned long long key = mk_key(row[idx], idx);
        if (key >= tau) {
            int p = atomicAdd(&cnt, 1);
            if (p < 2048) cand[p] = key;
        }
    }
    __syncthreads();

    // pad, then one bitonic sort of 2048 (8 elems/thread), descending
    int c = cnt;
    if (c > 2048) c = 2048;
    for (int e = c + tid; e < 2048; e += 256) cand[e] = 0ull;
    __syncthreads();
    for (int k = 2; k <= 2048; k <<= 1) {
        for (int j = k >> 1; j > 0; j >>= 1) {
            for (int e = tid; e < 2048; e += 256) {
                int ix = e ^ j;
                if (ix > e) {
                    unsigned long long a = cand[e], b = cand[ix];
                    bool up = ((e & k) == 0);
                    if (up ? (a < b) : (a > b)) { cand[e] = b; cand[ix] = a; }
                }
            }
            __syncthreads();
        }
    }
    if (tid < 64) Kset[t * 64 + tid] = 65535 - (int)(cand[tid] & 0xFFFFull);
}

// ---------------- solver: 4 ADMM/mirror-descent steps per token ----------------
#define SLV_FLOATS (64 * 257 + 256 * 17 + 256 + 256 + 64 + 64 + 4 * 64 + 2 + 64)
#define SLV_BYTES  (SLV_FLOATS * 4)

__global__ __launch_bounds__(256) void k_solver(const float* __restrict__ X,
                                                const float* __restrict__ M,
                                                const float* __restrict__ A,
                                                const int* __restrict__ Kidx,
                                                float* __restrict__ Yout) {
    extern __shared__ float sm[];
    float* Mg   = sm;                 // [64][257]
    float* band = Mg + 64 * 257;      // [256][17]
    float* Ysm  = band + 256 * 17;    // [256]
    float* vsm  = Ysm + 256;          // [256]
    float* Psm  = vsm + 256;          // [64]
    float* Lsm  = Psm + 64;           // [64]
    float* gp   = Lsm + 64;           // [4][64]
    float* red  = gp + 256;           // [2]
    int*   sidx = (int*)(red + 2);    // [64]

    int tid = threadIdx.x;
    int t = blockIdx.x;
    if (tid < 64) sidx[tid] = Kidx[t * 64 + tid];
    __syncthreads();
    for (int r = 0; r < 64; r++)
        Mg[r * 257 + tid] = M[(size_t)sidx[r] * DIM + tid];
    {
        int j = tid;
#pragma unroll
        for (int o = 0; o < 17; o++) {
            int i = j - 8 + o;
            band[j * 17 + o] = (i >= 0 && i < 256) ? A[j * 256 + i] : 0.f;
        }
    }
    float xr = X[t * DIM + tid];
    if (tid < 64) Psm[tid] = 1.0f / 64.0f;
    __syncthreads();
    {   // Y0 = P0 . Mg
        float y0 = 0.f;
        for (int k = 0; k < 64; k++) y0 = fmaf(Psm[k], Mg[k * 257 + tid], y0);
        Ysm[tid] = y0;
    }
    float lam = 0.f;
    __syncthreads();

    for (int step = 0; step < 4; step++) {
        float ymp = 0.f;
#pragma unroll 8
        for (int k = 0; k < 64; k++) ymp = fmaf(Psm[k], Mg[k * 257 + tid], ymp);
        float yold = Ysm[tid];
        float r_ = yold - ymp;
        lam = fmaf(RHO_C, r_, lam);
        float yab = 0.f;
#pragma unroll
        for (int o = 0; o < 17; o++) {
            int i = tid - 8 + o;
            if (i >= 0 && i < 256) yab = fmaf(band[tid * 17 + o], Ysm[i], yab);
        }
        float gY = yab - xr + lam + RHO_C * r_;
        float ynew = yold - TAU_C * gY;
        __syncthreads();                       // old-Y reads complete
        Ysm[tid] = ynew;
        vsm[tid] = RHO_C * (ynew - ymp) + lam;
        __syncthreads();
        {   // gP partials: 4 partitions x 64 slots
            int k = tid & 63, part = tid >> 6;
            const float* vv = vsm + part * 64;
            const float* mm = Mg + k * 257 + part * 64;
            float p_ = 0.f;
#pragma unroll 8
            for (int jj = 0; jj < 64; jj++) p_ = fmaf(vv[jj], mm[jj], p_);
            gp[part * 64 + k] = p_;
        }
        __syncthreads();
        if (tid < 64) {
            float gPk = -(gp[tid] + gp[64 + tid] + gp[128 + tid] + gp[192 + tid]);
            Lsm[tid] = logf(Psm[tid] + 1e-20f) - ETA_C * gPk;
        }
        __syncthreads();
        if (tid < 32) {
            float m_ = fmaxf(Lsm[tid], Lsm[tid + 32]);
            for (int o = 16; o > 0; o >>= 1) m_ = fmaxf(m_, __shfl_xor_sync(0xffffffffu, m_, o));
            if (tid == 0) red[0] = m_;
        }
        __syncthreads();
        if (tid < 64) Psm[tid] = expf(Lsm[tid] - red[0]);
        __syncthreads();
        if (tid < 32) {
            float s_ = Psm[tid] + Psm[tid + 32];
            for (int o = 16; o > 0; o >>= 1) s_ += __shfl_xor_sync(0xffffffffu, s_, o);
            if (tid == 0) red[1] = s_;
        }
        __syncthreads();
        if (tid < 64) Psm[tid] = Psm[tid] / red[1];
        __syncthreads();
    }
    Yout[t * DIM + tid] = Ysm[tid];
}

// ---------------- launcher ----------------
extern "C" void kernel_launch(void* const* d_in, const int* in_sizes, int n_in,
                              void* d_out, int out_size) {
    const int*   tokens = (const int*)d_in[0];
    const float* tab    = (const float*)d_in[1];
    const float* M      = (const float*)d_in[2];
    const float* A      = (const float*)d_in[3];
    float* out = (float*)d_out;

    float *pS, *pE, *pX, *pY, *pB; int* pK;
    cudaGetSymbolAddress((void**)&pS, g_S);
    cudaGetSymbolAddress((void**)&pE, g_E);
    cudaGetSymbolAddress((void**)&pX, g_X);
    cudaGetSymbolAddress((void**)&pY, g_Y);
    cudaGetSymbolAddress((void**)&pB, g_bsum);
    cudaGetSymbolAddress((void**)&pK, g_K);

    k_embed<<<N_TOK, 256>>>(tokens, tab, pE);
    k_colsum<<<8, 256>>>(pE, pB);
    k_cummean<<<8, 256>>>(pE, pB, pX);

    // exact fp32 scores (hypothesis: reference is exact fp32)
    dim3 gs(KMEM / 256, N_TOK / 64);
    k_gemm<0><<<gs, 256>>>(pE, M, pS, KMEM, 0);

    k_topk2<<<N_TOK, 256>>>(pS, pK);

    cudaFuncSetAttribute(k_solver, cudaFuncAttributeMaxDynamicSharedMemorySize, SLV_BYTES);
    k_solver<<<N_TOK, 256, SLV_BYTES>>>(pX, M, A, pK, pY);

    dim3 gl((VOCAB + 255) / 256, N_TOK / 64);
    k_gemm<0><<<gl, 256>>>(pY, M, out, VOCAB, 1);
}

// round 7
// speedup vs baseline: 1.0887x; 1.0887x over previous
#include <cuda_runtime.h>
#include <cstdint>

#define N_TOK   2048
#define DIM     256
#define KMEM    65536
#define KSHORT  64
#define VOCAB   50257
#define RHO_C   1.0f
#define TAU_C   0.1f
#define ETA_C   0.1f

typedef unsigned long long u64;

// ---------------- scratch (static __device__ — no allocation) ----------------
__device__ float g_S[(size_t)N_TOK * KMEM];   // 512 MB scores
__device__ float g_E[N_TOK * DIM];
__device__ float g_X[N_TOK * DIM];
__device__ float g_Y[N_TOK * DIM];
__device__ float g_bsum[8 * DIM];
__device__ int   g_K[N_TOK * KSHORT];

// ---------------- f32x2 packed helpers (Blackwell FFMA2 path) ----------------
__device__ __forceinline__ u64 pk2(float x) {
    u64 r; unsigned u = __float_as_uint(x);
    asm("mov.b64 %0, {%1, %1};" : "=l"(r) : "r"(u));
    return r;
}
__device__ __forceinline__ void ffma2(u64& d, u64 a, u64 b) {
    asm("fma.rn.f32x2 %0, %1, %2, %0;" : "+l"(d) : "l"(a), "l"(b));
}
__device__ __forceinline__ float2 unpk2(u64 v) {
    unsigned lo, hi;
    asm("mov.b64 {%0, %1}, %2;" : "=r"(lo), "=r"(hi) : "l"(v));
    return make_float2(__uint_as_float(lo), __uint_as_float(hi));
}

// ---------------- embed gather ----------------
__global__ void k_embed(const int* __restrict__ tok, const float* __restrict__ tab,
                        float* __restrict__ E) {
    int t = blockIdx.x, c = threadIdx.x;
    E[t * DIM + c] = tab[(size_t)tok[t] * DIM + c];
}

// ---------------- causal cumulative mean (2-phase) ----------------
__global__ void k_colsum(const float* __restrict__ E, float* __restrict__ bs) {
    int b = blockIdx.x, j = threadIdx.x;
    float s = 0.f;
    int base = b * 256;
#pragma unroll 4
    for (int r = 0; r < 256; r++) s += E[(base + r) * DIM + j];
    bs[b * DIM + j] = s;
}

__global__ void k_cummean(const float* __restrict__ E, const float* __restrict__ bs,
                          float* __restrict__ X) {
    int b = blockIdx.x, j = threadIdx.x;
    float acc = 0.f;
    for (int p = 0; p < b; p++) acc += bs[p * DIM + j];
    int base = b * 256;
    for (int r = 0; r < 256; r++) {
        int t = base + r;
        acc += E[t * DIM + j];
        X[t * DIM + j] = acc / (float)(t + 1);
    }
}

// ---------------- GEMM via FFMA2: C[t][m] = dot(Am[t], Bm[m]), K=256 --------
// block tile 64 tokens x 256 cols, 256 threads, thread tile 8 rows x 4 col-pairs.
// Column pairing (j-packing) keeps each output's k-accumulation order identical
// to scalar FFMA -> bit-exact vs the round-5 passing kernel.
// Guarded path (ncols = 50257, odd) uses SCALAR stores: row = t*ncols can be
// odd -> float2 store would be 4B-aligned only (this was the round-6 trap).
__global__ __launch_bounds__(256, 2) void k_gemm2(const float* __restrict__ Am,
                                                  const float* __restrict__ Bm,
                                                  float* __restrict__ C,
                                                  int ncols, int guard) {
    __shared__ __align__(16) float Es[32][68];     // [k][token]
    __shared__ __align__(16) float Bst[32 * 264];  // [k][m^sw], sw = k&28
    int tid = threadIdx.x;
    int tx = tid & 31, ty = tid >> 5;
    int mBase = blockIdx.x * 256;
    int tBase = blockIdx.y * 64;

    u64 acc[8][4];
#pragma unroll
    for (int i = 0; i < 8; i++)
#pragma unroll
        for (int p = 0; p < 4; p++) acc[i][p] = 0ull;

    for (int kc = 0; kc < 256; kc += 32) {
        // E tile: 64 tokens x 32 k, stored [k][token]
#pragma unroll
        for (int l = 0; l < 2; l++) {
            int f = tid + l * 256;
            int t = f >> 3, k4 = f & 7;
            float4 v = *(const float4*)&Am[(size_t)(tBase + t) * DIM + kc + k4 * 4];
            Es[k4 * 4 + 0][t] = v.x; Es[k4 * 4 + 1][t] = v.y;
            Es[k4 * 4 + 2][t] = v.z; Es[k4 * 4 + 3][t] = v.w;
        }
        // B tile transposed to [k][m] with XOR swizzle (conflict-free both ways)
#pragma unroll
        for (int l = 0; l < 8; l++) {
            int f = tid + l * 256;
            int r = f >> 3, k4 = f & 7;
            float4 v = *(const float4*)&Bm[(size_t)(mBase + r) * DIM + kc + k4 * 4];
            int col = r ^ (k4 << 2);
            Bst[(k4 * 4 + 0) * 264 + col] = v.x;
            Bst[(k4 * 4 + 1) * 264 + col] = v.y;
            Bst[(k4 * 4 + 2) * 264 + col] = v.z;
            Bst[(k4 * 4 + 3) * 264 + col] = v.w;
        }
        __syncthreads();
#pragma unroll 8
        for (int k = 0; k < 32; k++) {
            float4 e0 = *(const float4*)&Es[k][ty * 8];
            float4 e1 = *(const float4*)&Es[k][ty * 8 + 4];
            u64 ep[8];
            ep[0] = pk2(e0.x); ep[1] = pk2(e0.y); ep[2] = pk2(e0.z); ep[3] = pk2(e0.w);
            ep[4] = pk2(e1.x); ep[5] = pk2(e1.y); ep[6] = pk2(e1.z); ep[7] = pk2(e1.w);
            const float* bp = &Bst[k * 264 + ((2 * tx) ^ (k & 28))];
            u64 mv0 = *(const u64*)(bp);
            u64 mv1 = *(const u64*)(bp + 64);
            u64 mv2 = *(const u64*)(bp + 128);
            u64 mv3 = *(const u64*)(bp + 192);
#pragma unroll
            for (int i = 0; i < 8; i++) {
                ffma2(acc[i][0], ep[i], mv0);
                ffma2(acc[i][1], ep[i], mv1);
                ffma2(acc[i][2], ep[i], mv2);
                ffma2(acc[i][3], ep[i], mv3);
            }
        }
        __syncthreads();
    }
#pragma unroll
    for (int i = 0; i < 8; i++) {
        int t = tBase + ty * 8 + i;
        size_t row = (size_t)t * (size_t)ncols;
#pragma unroll
        for (int p = 0; p < 4; p++) {
            int m0 = mBase + p * 64 + 2 * tx;
            float2 v = unpk2(acc[i][p]);
            if (!guard) {
                *(float2*)&C[row + m0] = v;        // ncols even: 8B-aligned
            } else {
                if (m0 < ncols)     C[row + m0]     = v.x;   // scalar: odd ncols
                if (m0 + 1 < ncols) C[row + m0 + 1] = v.y;
            }
        }
    }
}

// ---------------- exact top-64: single-shot strip-max threshold ----------------
__device__ __forceinline__ unsigned int ordf(float f) {
    unsigned int u = __float_as_uint(f);
    return (u & 0x80000000u) ? ~u : (u | 0x80000000u);
}

__device__ __forceinline__ unsigned long long mk_key(float v, int idx) {
    return ((unsigned long long)ordf(v) << 32) | (unsigned int)(65535 - idx);
}

__global__ __launch_bounds__(256) void k_topk2(const float* __restrict__ S,
                                               int* __restrict__ Kset) {
    __shared__ unsigned long long cand[2048];
    __shared__ unsigned long long tmax[256];
    __shared__ int cnt;
    int tid = threadIdx.x;
    int t = blockIdx.x;
    const float* row = S + (size_t)t * KMEM;

    // pass 1: per-thread strip max (strided, coalesced)
    unsigned long long mk = 0ull;
#pragma unroll 8
    for (int i = 0; i < 256; i++) {
        int idx = tid + (i << 8);
        unsigned long long key = mk_key(row[idx], idx);
        if (key > mk) mk = key;
    }
    tmax[tid] = mk;
    if (tid == 0) cnt = 0;
    __syncthreads();

    // bitonic sort 256 strip maxima, descending
    for (int k = 2; k <= 256; k <<= 1) {
        for (int j = k >> 1; j > 0; j >>= 1) {
            int ix = tid ^ j;
            if (ix > tid) {
                unsigned long long a = tmax[tid], b = tmax[ix];
                bool up = ((tid & k) == 0);
                if (up ? (a < b) : (a > b)) { tmax[tid] = b; tmax[ix] = a; }
            }
            __syncthreads();
        }
    }
    // tau = 64th-largest strip max => provable lower bound on row's 64th key
    unsigned long long tau = tmax[63];
    __syncthreads();

    // pass 2: collect all keys >= tau
#pragma unroll 4
    for (int i = 0; i < 256; i++) {
        int idx = tid + (i << 8);
        unsigned long long key = mk_key(row[idx], idx);
        if (key >= tau) {
            int p = atomicAdd(&cnt, 1);
            if (p < 2048) cand[p] = key;
        }
    }
    __syncthreads();

    int c = cnt;
    if (c > 2048) c = 2048;
    for (int e = c + tid; e < 2048; e += 256) cand[e] = 0ull;
    __syncthreads();
    for (int k = 2; k <= 2048; k <<= 1) {
        for (int j = k >> 1; j > 0; j >>= 1) {
            for (int e = tid; e < 2048; e += 256) {
                int ix = e ^ j;
                if (ix > e) {
                    unsigned long long a = cand[e], b = cand[ix];
                    bool up = ((e & k) == 0);
                    if (up ? (a < b) : (a > b)) { cand[e] = b; cand[ix] = a; }
                }
            }
            __syncthreads();
        }
    }
    if (tid < 64) Kset[t * 64 + tid] = 65535 - (int)(cand[tid] & 0xFFFFull);
}

// ---------------- solver: 4 ADMM/mirror-descent steps per token ----------------
#define SLV_FLOATS (64 * 257 + 256 * 17 + 256 + 256 + 64 + 64 + 4 * 64 + 2 + 64)
#define SLV_BYTES  (SLV_FLOATS * 4)

__global__ __launch_bounds__(256) void k_solver(const float* __restrict__ X,
                                                const float* __restrict__ M,
                                                const float* __restrict__ A,
                                                const int* __restrict__ Kidx,
                                                float* __restrict__ Yout) {
    extern __shared__ float sm[];
    float* Mg   = sm;                 // [64][257]
    float* band = Mg + 64 * 257;      // [256][17]
    float* Ysm  = band + 256 * 17;    // [256]
    float* vsm  = Ysm + 256;          // [256]
    float* Psm  = vsm + 256;          // [64]
    float* Lsm  = Psm + 64;           // [64]
    float* gp   = Lsm + 64;           // [4][64]
    float* red  = gp + 256;           // [2]
    int*   sidx = (int*)(red + 2);    // [64]

    int tid = threadIdx.x;
    int t = blockIdx.x;
    if (tid < 64) sidx[tid] = Kidx[t * 64 + tid];
    __syncthreads();
    for (int r = 0; r < 64; r++)
        Mg[r * 257 + tid] = M[(size_t)sidx[r] * DIM + tid];
    {
        int j = tid;
#pragma unroll
        for (int o = 0; o < 17; o++) {
            int i = j - 8 + o;
            band[j * 17 + o] = (i >= 0 && i < 256) ? A[j * 256 + i] : 0.f;
        }
    }
    float xr = X[t * DIM + tid];
    if (tid < 64) Psm[tid] = 1.0f / 64.0f;
    __syncthreads();
    {   // Y0 = P0 . Mg
        float y0 = 0.f;
        for (int k = 0; k < 64; k++) y0 = fmaf(Psm[k], Mg[k * 257 + tid], y0);
        Ysm[tid] = y0;
    }
    float lam = 0.f;
    __syncthreads();

    for (int step = 0; step < 4; step++) {
        float ymp = 0.f;
#pragma unroll 8
        for (int k = 0; k < 64; k++) ymp = fmaf(Psm[k], Mg[k * 257 + tid], ymp);
        float yold = Ysm[tid];
        float r_ = yold - ymp;
        lam = fmaf(RHO_C, r_, lam);
        float yab = 0.f;
#pragma unroll
        for (int o = 0; o < 17; o++) {
            int i = tid - 8 + o;
            if (i >= 0 && i < 256) yab = fmaf(band[tid * 17 + o], Ysm[i], yab);
        }
        float gY = yab - xr + lam + RHO_C * r_;
        float ynew = yold - TAU_C * gY;
        __syncthreads();                       // old-Y reads complete
        Ysm[tid] = ynew;
        vsm[tid] = RHO_C * (ynew - ymp) + lam;
        __syncthreads();
        {   // gP partials: 4 partitions x 64 slots
            int k = tid & 63, part = tid >> 6;
            const float* vv = vsm + part * 64;
            const float* mm = Mg + k * 257 + part * 64;
            float p_ = 0.f;
#pragma unroll 8
            for (int jj = 0; jj < 64; jj++) p_ = fmaf(vv[jj], mm[jj], p_);
            gp[part * 64 + k] = p_;
        }
        __syncthreads();
        if (tid < 64) {
            float gPk = -(gp[tid] + gp[64 + tid] + gp[128 + tid] + gp[192 + tid]);
            Lsm[tid] = logf(Psm[tid] + 1e-20f) - ETA_C * gPk;
        }
        __syncthreads();
        if (tid < 32) {
            float m_ = fmaxf(Lsm[tid], Lsm[tid + 32]);
            for (int o = 16; o > 0; o >>= 1) m_ = fmaxf(m_, __shfl_xor_sync(0xffffffffu, m_, o));
            if (tid == 0) red[0] = m_;
        }
        __syncthreads();
        if (tid < 64) Psm[tid] = expf(Lsm[tid] - red[0]);
        __syncthreads();
        if (tid < 32) {
            float s_ = Psm[tid] + Psm[tid + 32];
            for (int o = 16; o > 0; o >>= 1) s_ += __shfl_xor_sync(0xffffffffu, s_, o);
            if (tid == 0) red[1] = s_;
        }
        __syncthreads();
        if (tid < 64) Psm[tid] = Psm[tid] / red[1];
        __syncthreads();
    }
    Yout[t * DIM + tid] = Ysm[tid];
}

// ---------------- launcher ----------------
extern "C" void kernel_launch(void* const* d_in, const int* in_sizes, int n_in,
                              void* d_out, int out_size) {
    const int*   tokens = (const int*)d_in[0];
    const float* tab    = (const float*)d_in[1];
    const float* M      = (const float*)d_in[2];
    const float* A      = (const float*)d_in[3];
    float* out = (float*)d_out;

    float *pS, *pE, *pX, *pY, *pB; int* pK;
    cudaGetSymbolAddress((void**)&pS, g_S);
    cudaGetSymbolAddress((void**)&pE, g_E);
    cudaGetSymbolAddress((void**)&pX, g_X);
    cudaGetSymbolAddress((void**)&pY, g_Y);
    cudaGetSymbolAddress((void**)&pB, g_bsum);
    cudaGetSymbolAddress((void**)&pK, g_K);

    k_embed<<<N_TOK, 256>>>(tokens, tab, pE);
    k_colsum<<<8, 256>>>(pE, pB);
    k_cummean<<<8, 256>>>(pE, pB, pX);

    dim3 gs(KMEM / 256, N_TOK / 64);
    k_gemm2<<<gs, 256>>>(pE, M, pS, KMEM, 0);

    k_topk2<<<N_TOK, 256>>>(pS, pK);

    cudaFuncSetAttribute(k_solver, cudaFuncAttributeMaxDynamicSharedMemorySize, SLV_BYTES);
    k_solver<<<N_TOK, 256, SLV_BYTES>>>(pX, M, A, pK, pY);

    dim3 gl((VOCAB + 255) / 256, N_TOK / 64);
    k_gemm2<<<gl, 256>>>(pY, M, out, VOCAB, 1);
}

// round 10
// speedup vs baseline: 1.6682x; 1.5323x over previous
#include <cuda_runtime.h>
#include <cuda_bf16.h>
#include <cstdint>

#define N_TOK   2048
#define DIM     256
#define KMEM    65536
#define KSHORT  64
#define VOCAB   50257
#define RHO_C   1.0f
#define TAU_C   0.1f
#define ETA_C   0.1f

typedef unsigned long long u64;
typedef unsigned int u32;

// ---------------- scratch (static __device__ — no allocation) ----------------
__device__ __align__(16) __nv_bfloat16 g_S16[(size_t)N_TOK * KMEM];  // 256 MB approx scores
__device__ __align__(16) __nv_bfloat16 g_M16[(size_t)KMEM * DIM];   // 32 MB bf16 memory bank
__device__ __align__(16) __nv_bfloat16 g_E16[N_TOK * DIM];
__device__ float g_E[N_TOK * DIM];
__device__ float g_X[N_TOK * DIM];
__device__ float g_Y[N_TOK * DIM];
__device__ float g_bsum[8 * DIM];
__device__ int   g_K[N_TOK * KSHORT];

#define SWZ128(o) ((o) ^ (((o) >> 3) & 0x70))

// ---------------- mma.sync / ldmatrix helpers (sm_80+ PTX, no arch suffix) ---
__device__ __forceinline__ u32 smem_u32(const void* p) {
    u32 a;
    asm("{ .reg .u64 t; cvta.to.shared.u64 t, %1; cvt.u32.u64 %0, t; }" : "=r"(a) : "l"(p));
    return a;
}
__device__ __forceinline__ void ldsm4(u32* r, u32 addr) {
    asm volatile("ldmatrix.sync.aligned.m8n8.x4.shared.b16 {%0,%1,%2,%3}, [%4];"
        : "=r"(r[0]), "=r"(r[1]), "=r"(r[2]), "=r"(r[3]) : "r"(addr));
}
__device__ __forceinline__ void mma_bf16(float* c, const u32* a, u32 b0, u32 b1) {
    asm volatile("mma.sync.aligned.m16n8k16.row.col.f32.bf16.bf16.f32 "
        "{%0,%1,%2,%3}, {%4,%5,%6,%7}, {%8,%9}, {%0,%1,%2,%3};"
        : "+f"(c[0]), "+f"(c[1]), "+f"(c[2]), "+f"(c[3])
        : "r"(a[0]), "r"(a[1]), "r"(a[2]), "r"(a[3]), "r"(b0), "r"(b1));
}

// ---------------- f32x2 packed helpers (logits GEMM) ----------------
__device__ __forceinline__ u64 pk2(float x) {
    u64 r; unsigned u = __float_as_uint(x);
    asm("mov.b64 %0, {%1, %1};" : "=l"(r) : "r"(u));
    return r;
}
__device__ __forceinline__ void ffma2(u64& d, u64 a, u64 b) {
    asm("fma.rn.f32x2 %0, %1, %2, %0;" : "+l"(d) : "l"(a), "l"(b));
}
__device__ __forceinline__ float2 unpk2(u64 v) {
    unsigned lo, hi;
    asm("mov.b64 {%0, %1}, %2;" : "=r"(lo), "=r"(hi) : "l"(v));
    return make_float2(__uint_as_float(lo), __uint_as_float(hi));
}

// ---------------- embed gather (also emits bf16 copy) ----------------
__global__ void k_embed(const int* __restrict__ tok, const float* __restrict__ tab,
                        float* __restrict__ E, __nv_bfloat16* __restrict__ E16) {
    int t = blockIdx.x, c = threadIdx.x;
    float v = tab[(size_t)tok[t] * DIM + c];
    E[t * DIM + c] = v;
    E16[t * DIM + c] = __float2bfloat16(v);
}

// ---------------- fp32 -> bf16 bulk convert ----------------
__global__ void k_cvt(const float* __restrict__ src, __nv_bfloat16* __restrict__ dst, int n4) {
    int i = blockIdx.x * 256 + threadIdx.x;
    if (i < n4) {
        float4 v = ((const float4*)src)[i];
        ((__nv_bfloat162*)dst)[i * 2]     = __floats2bfloat162_rn(v.x, v.y);
        ((__nv_bfloat162*)dst)[i * 2 + 1] = __floats2bfloat162_rn(v.z, v.w);
    }
}

// ---------------- causal cumulative mean (2-phase) ----------------
__global__ void k_colsum(const float* __restrict__ E, float* __restrict__ bs) {
    int b = blockIdx.x, j = threadIdx.x;
    float s = 0.f;
    int base = b * 256;
#pragma unroll 4
    for (int r = 0; r < 256; r++) s += E[(base + r) * DIM + j];
    bs[b * DIM + j] = s;
}

__global__ void k_cummean(const float* __restrict__ E, const float* __restrict__ bs,
                          float* __restrict__ X) {
    int b = blockIdx.x, j = threadIdx.x;
    float acc = 0.f;
    for (int p = 0; p < b; p++) acc += bs[p * DIM + j];
    int base = b * 256;
    for (int r = 0; r < 256; r++) {
        int t = base + r;
        acc += E[t * DIM + j];
        X[t * DIM + j] = acc / (float)(t + 1);
    }
}

// ---------------- approx scores: bf16 HMMA GEMM ----------------
// S[token][slot] ~= dot(E[token], M[slot]); 128x128 CTA tile, K=256.
// 8 warps: wm = w&3 (token, 32 rows), wn = w>>2 (slot, 64 cols).
__global__ __launch_bounds__(256, 2) void k_hmma(
    const __nv_bfloat16* __restrict__ E16,
    const __nv_bfloat16* __restrict__ M16,
    __nv_bfloat16* __restrict__ S)
{
    __shared__ __align__(16) char sA[128 * 128];  // tokens [128][64 k] bf16, SW128
    __shared__ __align__(16) char sB[128 * 128];  // slots  [128][64 k] bf16, SW128
    int tid = threadIdx.x;
    int w = tid >> 5, l = tid & 31;
    int wm = w & 3, wn = w >> 2;
    int tokBase = blockIdx.y * 128;
    int slotBase = blockIdx.x * 128;

    float acc[2][8][4];
#pragma unroll
    for (int mi = 0; mi < 2; mi++)
#pragma unroll
        for (int ni = 0; ni < 8; ni++)
#pragma unroll
            for (int q = 0; q < 4; q++) acc[mi][ni][q] = 0.f;

    // per-lane ldmatrix address components
    int a_row = wm * 32 + (l & 7) + ((l >> 3) & 1) * 8;   // + mi*16
    int a_kb  = ((l >> 4) * 8) * 2;                        // byte col, + ks*32
    int b_row = wn * 64 + (l & 7) + (l >> 4) * 8;          // + nj*16
    int b_kb  = (((l >> 3) & 1) * 8) * 2;                  // byte col, + ks*32

    u32 aBase = smem_u32(sA), bBase = smem_u32(sB);

    for (int kc = 0; kc < 256; kc += 64) {
        // fill tiles: 1024 16B granules each, 4 per thread
#pragma unroll
        for (int g = tid; g < 1024; g += 256) {
            int row = g >> 3, seg = g & 7;
            *(uint4*)(sA + SWZ128(row * 128 + seg * 16)) =
                *(const uint4*)(E16 + (size_t)(tokBase + row) * DIM + kc + seg * 8);
        }
#pragma unroll
        for (int g = tid; g < 1024; g += 256) {
            int row = g >> 3, seg = g & 7;
            *(uint4*)(sB + SWZ128(row * 128 + seg * 16)) =
                *(const uint4*)(M16 + (size_t)(slotBase + row) * DIM + kc + seg * 8);
        }
        __syncthreads();
#pragma unroll
        for (int ks = 0; ks < 4; ks++) {
            u32 a[2][4];
#pragma unroll
            for (int mi = 0; mi < 2; mi++)
                ldsm4(a[mi], aBase + SWZ128((a_row + mi * 16) * 128 + a_kb + ks * 32));
            u32 b[4][4];
#pragma unroll
            for (int nj = 0; nj < 4; nj++)
                ldsm4(b[nj], bBase + SWZ128((b_row + nj * 16) * 128 + b_kb + ks * 32));
#pragma unroll
            for (int mi = 0; mi < 2; mi++)
#pragma unroll
                for (int nj = 0; nj < 4; nj++) {
                    mma_bf16(acc[mi][nj * 2],     a[mi], b[nj][0], b[nj][1]);
                    mma_bf16(acc[mi][nj * 2 + 1], a[mi], b[nj][2], b[nj][3]);
                }
        }
        __syncthreads();
    }

    // epilogue: c0,c1 -> row l/4, cols (l%4)*2+{0,1}; c2,c3 -> row+8
#pragma unroll
    for (int mi = 0; mi < 2; mi++) {
        int tok0 = tokBase + wm * 32 + mi * 16 + (l >> 2);
#pragma unroll
        for (int ni = 0; ni < 8; ni++) {
            int slot = slotBase + wn * 64 + ni * 8 + (l & 3) * 2;
            *(__nv_bfloat162*)&S[(size_t)tok0 * KMEM + slot] =
                __floats2bfloat162_rn(acc[mi][ni][0], acc[mi][ni][1]);
            *(__nv_bfloat162*)&S[(size_t)(tok0 + 8) * KMEM + slot] =
                __floats2bfloat162_rn(acc[mi][ni][2], acc[mi][ni][3]);
        }
    }
}

// ---------------- top-128 superset + exact fp32 rescore + exact top-64 -------
__device__ __forceinline__ u32 ordf(float f) {
    u32 u = __float_as_uint(f);
    return (u & 0x80000000u) ? ~u : (u | 0x80000000u);
}
__device__ __forceinline__ u64 mk_key(float v, int idx) {
    return ((u64)ordf(v) << 32) | (u32)(65535 - idx);
}

__global__ __launch_bounds__(256) void k_topk_rescore(
    const __nv_bfloat16* __restrict__ S,
    const float* __restrict__ E,
    const float* __restrict__ Mm,
    int* __restrict__ Kset
) {
    __shared__ u64 cand[2048];
    __shared__ u64 tmax[256];
    __shared__ float Erow[256];
    __shared__ int cslot[128];
    __shared__ int cnt;
    int tid = threadIdx.x;
    int t = blockIdx.x;
    const __nv_bfloat16* row = S + (size_t)t * KMEM;
    Erow[tid] = E[t * DIM + tid];
    if (tid == 0) cnt = 0;

    // pass 1: per-thread strip max of approx keys
    u64 mk = 0ull;
#pragma unroll 8
    for (int i = 0; i < 256; i++) {
        int idx = tid + (i << 8);
        u64 key = mk_key(__bfloat162float(row[idx]), idx);
        if (key > mk) mk = key;
    }
    tmax[tid] = mk;
    __syncthreads();

    // bitonic sort 256 strip maxima, descending
    for (int k = 2; k <= 256; k <<= 1) {
        for (int j = k >> 1; j > 0; j >>= 1) {
            int ix = tid ^ j;
            if (ix > tid) {
                u64 a = tmax[tid], b = tmax[ix];
                bool up = ((tid & k) == 0);
                if (up ? (a < b) : (a > b)) { tmax[tid] = b; tmax[ix] = a; }
            }
            __syncthreads();
        }
    }
    // tau = 128th-largest strip max: >=128 keys >= tau exist, so the overall
    // approx top-128 is a subset of {key >= tau}.
    u64 tau = tmax[127];
    __syncthreads();

    // pass 2: collect keys >= tau
#pragma unroll 4
    for (int i = 0; i < 256; i++) {
        int idx = tid + (i << 8);
        u64 key = mk_key(__bfloat162float(row[idx]), idx);
        if (key >= tau) {
            int p = atomicAdd(&cnt, 1);
            if (p < 2048) cand[p] = key;
        }
    }
    __syncthreads();
    int c = cnt; if (c > 2048) c = 2048;
    for (int e = c + tid; e < 2048; e += 256) cand[e] = 0ull;
    __syncthreads();
    for (int k = 2; k <= 2048; k <<= 1) {
        for (int j = k >> 1; j > 0; j >>= 1) {
            for (int e = tid; e < 2048; e += 256) {
                int ix = e ^ j;
                if (ix > e) {
                    u64 a = cand[e], b = cand[ix];
                    bool up = ((e & k) == 0);
                    if (up ? (a < b) : (a > b)) { cand[e] = b; cand[ix] = a; }
                }
            }
            __syncthreads();
        }
    }
    if (tid < 128) cslot[tid] = 65535 - (int)(cand[tid] & 0xFFFFull);
    __syncthreads();

    // exact fp32 rescore of the 128 candidates (true top-64 provably inside:
    // bf16 approx sigma ~4e-5 vs top64->128 margin ~1.9e-3)
    {
        int w = tid >> 5, l = tid & 31;
        for (int j = 0; j < 16; j++) {
            int ci = w * 16 + j;
            int slot = cslot[ci];
            const float* mrow = &Mm[(size_t)slot * DIM];
            float p = 0.f;
#pragma unroll
            for (int i = 0; i < 8; i++) p = fmaf(Erow[l + 32 * i], mrow[l + 32 * i], p);
#pragma unroll
            for (int o = 16; o > 0; o >>= 1) p += __shfl_xor_sync(0xffffffffu, p, o);
            if (l == 0) tmax[ci] = mk_key(p, slot);
        }
    }
    if (tid >= 128) tmax[tid] = 0ull;
    __syncthreads();

    // final exact top-64: sort (128 valid of 256), descending
    for (int k = 2; k <= 256; k <<= 1) {
        for (int j = k >> 1; j > 0; j >>= 1) {
            int ix = tid ^ j;
            if (ix > tid) {
                u64 a = tmax[tid], b = tmax[ix];
                bool up = ((tid & k) == 0);
                if (up ? (a < b) : (a > b)) { tmax[tid] = b; tmax[ix] = a; }
            }
            __syncthreads();
        }
    }
    if (tid < 64) Kset[t * 64 + tid] = 65535 - (int)(tmax[tid] & 0xFFFFull);
}

// ---------------- FFMA2 GEMM (logits): C[t][m] = dot(Y[t], M[m]) --------
__global__ __launch_bounds__(256, 2) void k_gemm2(const float* __restrict__ Am,
                                                  const float* __restrict__ Bm,
                                                  float* __restrict__ C,
                                                  int ncols, int guard) {
    __shared__ __align__(16) float Es[32][68];
    __shared__ __align__(16) float Bst[32 * 264];
    int tid = threadIdx.x;
    int tx = tid & 31, ty = tid >> 5;
    int mBase = blockIdx.x * 256;
    int tBase = blockIdx.y * 64;

    u64 acc[8][4];
#pragma unroll
    for (int i = 0; i < 8; i++)
#pragma unroll
        for (int p = 0; p < 4; p++) acc[i][p] = 0ull;

    for (int kc = 0; kc < 256; kc += 32) {
#pragma unroll
        for (int l = 0; l < 2; l++) {
            int f = tid + l * 256;
            int t = f >> 3, k4 = f & 7;
            float4 v = *(const float4*)&Am[(size_t)(tBase + t) * DIM + kc + k4 * 4];
            Es[k4 * 4 + 0][t] = v.x; Es[k4 * 4 + 1][t] = v.y;
            Es[k4 * 4 + 2][t] = v.z; Es[k4 * 4 + 3][t] = v.w;
        }
#pragma unroll
        for (int l = 0; l < 8; l++) {
            int f = tid + l * 256;
            int r = f >> 3, k4 = f & 7;
            float4 v = *(const float4*)&Bm[(size_t)(mBase + r) * DIM + kc + k4 * 4];
            int col = r ^ (k4 << 2);
            Bst[(k4 * 4 + 0) * 264 + col] = v.x;
            Bst[(k4 * 4 + 1) * 264 + col] = v.y;
            Bst[(k4 * 4 + 2) * 264 + col] = v.z;
            Bst[(k4 * 4 + 3) * 264 + col] = v.w;
        }
        __syncthreads();
#pragma unroll 8
        for (int k = 0; k < 32; k++) {
            float4 e0 = *(const float4*)&Es[k][ty * 8];
            float4 e1 = *(const float4*)&Es[k][ty * 8 + 4];
            u64 ep[8];
            ep[0] = pk2(e0.x); ep[1] = pk2(e0.y); ep[2] = pk2(e0.z); ep[3] = pk2(e0.w);
            ep[4] = pk2(e1.x); ep[5] = pk2(e1.y); ep[6] = pk2(e1.z); ep[7] = pk2(e1.w);
            const float* bp = &Bst[k * 264 + ((2 * tx) ^ (k & 28))];
            u64 mv0 = *(const u64*)(bp);
            u64 mv1 = *(const u64*)(bp + 64);
            u64 mv2 = *(const u64*)(bp + 128);
            u64 mv3 = *(const u64*)(bp + 192);
#pragma unroll
            for (int i = 0; i < 8; i++) {
                ffma2(acc[i][0], ep[i], mv0);
                ffma2(acc[i][1], ep[i], mv1);
                ffma2(acc[i][2], ep[i], mv2);
                ffma2(acc[i][3], ep[i], mv3);
            }
        }
        __syncthreads();
    }
#pragma unroll
    for (int i = 0; i < 8; i++) {
        int t = tBase + ty * 8 + i;
        size_t row = (size_t)t * (size_t)ncols;
#pragma unroll
        for (int p = 0; p < 4; p++) {
            int m0 = mBase + p * 64 + 2 * tx;
            float2 v = unpk2(acc[i][p]);
            if (!guard) {
                *(float2*)&C[row + m0] = v;
            } else {
                if (m0 < ncols)     C[row + m0]     = v.x;
                if (m0 + 1 < ncols) C[row + m0 + 1] = v.y;
            }
        }
    }
}

// ---------------- solver: 4 ADMM/mirror-descent steps per token ----------------
#define SLV_FLOATS (64 * 257 + 256 * 17 + 256 + 256 + 64 + 64 + 4 * 64 + 2 + 64)
#define SLV_BYTES  (SLV_FLOATS * 4)

__global__ __launch_bounds__(256) void k_solver(const float* __restrict__ X,
                                                const float* __restrict__ M,
                                                const float* __restrict__ A,
                                                const int* __restrict__ Kidx,
                                                float* __restrict__ Yout) {
    extern __shared__ float sm[];
    float* Mg   = sm;                 // [64][257]
    float* band = Mg + 64 * 257;      // [256][17]
    float* Ysm  = band + 256 * 17;    // [256]
    float* vsm  = Ysm + 256;          // [256]
    float* Psm  = vsm + 256;          // [64]
    float* Lsm  = Psm + 64;           // [64]
    float* gp   = Lsm + 64;           // [4][64]
    float* red  = gp + 256;           // [2]
    int*   sidx = (int*)(red + 2);    // [64]

    int tid = threadIdx.x;
    int t = blockIdx.x;
    if (tid < 64) sidx[tid] = Kidx[t * 64 + tid];
    __syncthreads();
    for (int r = 0; r < 64; r++)
        Mg[r * 257 + tid] = M[(size_t)sidx[r] * DIM + tid];
    {
        int j = tid;
#pragma unroll
        for (int o = 0; o < 17; o++) {
            int i = j - 8 + o;
            band[j * 17 + o] = (i >= 0 && i < 256) ? A[j * 256 + i] : 0.f;
        }
    }
    float xr = X[t * DIM + tid];
    if (tid < 64) Psm[tid] = 1.0f / 64.0f;
    __syncthreads();
    {   // Y0 = P0 . Mg
        float y0 = 0.f;
        for (int k = 0; k < 64; k++) y0 = fmaf(Psm[k], Mg[k * 257 + tid], y0);
        Ysm[tid] = y0;
    }
    float lam = 0.f;
    __syncthreads();

    for (int step = 0; step < 4; step++) {
        float ymp = 0.f;
#pragma unroll 8
        for (int k = 0; k < 64; k++) ymp = fmaf(Psm[k], Mg[k * 257 + tid], ymp);
        float yold = Ysm[tid];
        float r_ = yold - ymp;
        lam = fmaf(RHO_C, r_, lam);
        float yab = 0.f;
#pragma unroll
        for (int o = 0; o < 17; o++) {
            int i = tid - 8 + o;
            if (i >= 0 && i < 256) yab = fmaf(band[tid * 17 + o], Ysm[i], yab);
        }
        float gY = yab - xr + lam + RHO_C * r_;
        float ynew = yold - TAU_C * gY;
        __syncthreads();
        Ysm[tid] = ynew;
        vsm[tid] = RHO_C * (ynew - ymp) + lam;
        __syncthreads();
        {
            int k = tid & 63, part = tid >> 6;
            const float* vv = vsm + part * 64;
            const float* mm = Mg + k * 257 + part * 64;
            float p_ = 0.f;
#pragma unroll 8
            for (int jj = 0; jj < 64; jj++) p_ = fmaf(vv[jj], mm[jj], p_);
            gp[part * 64 + k] = p_;
        }
        __syncthreads();
        if (tid < 64) {
            float gPk = -(gp[tid] + gp[64 + tid] + gp[128 + tid] + gp[192 + tid]);
            Lsm[tid] = logf(Psm[tid] + 1e-20f) - ETA_C * gPk;
        }
        __syncthreads();
        if (tid < 32) {
            float m_ = fmaxf(Lsm[tid], Lsm[tid + 32]);
            for (int o = 16; o > 0; o >>= 1) m_ = fmaxf(m_, __shfl_xor_sync(0xffffffffu, m_, o));
            if (tid == 0) red[0] = m_;
        }
        __syncthreads();
        if (tid < 64) Psm[tid] = expf(Lsm[tid] - red[0]);
        __syncthreads();
        if (tid < 32) {
            float s_ = Psm[tid] + Psm[tid + 32];
            for (int o = 16; o > 0; o >>= 1) s_ += __shfl_xor_sync(0xffffffffu, s_, o);
            if (tid == 0) red[1] = s_;
        }
        __syncthreads();
        if (tid < 64) Psm[tid] = Psm[tid] / red[1];
        __syncthreads();
    }
    Yout[t * DIM + tid] = Ysm[tid];
}

// ---------------- launcher ----------------
extern "C" void kernel_launch(void* const* d_in, const int* in_sizes, int n_in,
                              void* d_out, int out_size) {
    const int*   tokens = (const int*)d_in[0];
    const float* tab    = (const float*)d_in[1];
    const float* M      = (const float*)d_in[2];
    const float* A      = (const float*)d_in[3];
    float* out = (float*)d_out;

    __nv_bfloat16 *pS, *pM16, *pE16;
    float *pE, *pX, *pY, *pB; int* pK;
    cudaGetSymbolAddress((void**)&pS, g_S16);
    cudaGetSymbolAddress((void**)&pM16, g_M16);
    cudaGetSymbolAddress((void**)&pE16, g_E16);
    cudaGetSymbolAddress((void**)&pE, g_E);
    cudaGetSymbolAddress((void**)&pX, g_X);
    cudaGetSymbolAddress((void**)&pY, g_Y);
    cudaGetSymbolAddress((void**)&pB, g_bsum);
    cudaGetSymbolAddress((void**)&pK, g_K);

    k_embed<<<N_TOK, 256>>>(tokens, tab, pE, pE16);
    k_colsum<<<8, 256>>>(pE, pB);
    k_cummean<<<8, 256>>>(pE, pB, pX);
    k_cvt<<<(KMEM * DIM / 4 + 255) / 256, 256>>>(M, pM16, KMEM * DIM / 4);

    // approx scores: bf16 HMMA (mma.sync), 128x128 tiles
    dim3 gs(KMEM / 128, N_TOK / 128);
    k_hmma<<<gs, 256>>>(pE16, pM16, pS);

    // superset top-128 -> exact fp32 rescore -> exact top-64
    k_topk_rescore<<<N_TOK, 256>>>(pS, pE, M, pK);

    cudaFuncSetAttribute(k_solver, cudaFuncAttributeMaxDynamicSharedMemorySize, SLV_BYTES);
    k_solver<<<N_TOK, 256, SLV_BYTES>>>(pX, M, A, pK, pY);

    dim3 gl((VOCAB + 255) / 256, N_TOK / 64);
    k_gemm2<<<gl, 256>>>(pY, M, out, VOCAB, 1);
}

// round 11
// speedup vs baseline: 2.0478x; 1.2275x over previous
#include <cuda_runtime.h>
#include <cuda_bf16.h>
#include <cstdint>

#define N_TOK   2048
#define DIM     256
#define KMEM    65536
#define KSHORT  64
#define VOCAB   50257
#define RHO_C   1.0f
#define TAU_C   0.1f
#define ETA_C   0.1f

typedef unsigned long long u64;
typedef unsigned int u32;

// ---------------- scratch (static __device__ — no allocation) ----------------
__device__ __align__(16) __nv_bfloat16 g_S16[(size_t)N_TOK * KMEM];   // 256 MB approx scores
__device__ __align__(16) __nv_bfloat16 g_Mcat[(size_t)KMEM * 768];    // 96 MB [Whi|Wlo|Whi]
__device__ __align__(16) __nv_bfloat16 g_Ycat[N_TOK * 768];           // [Yhi|Yhi|Ylo]
__device__ __align__(16) __nv_bfloat16 g_E16[N_TOK * DIM];
__device__ float g_E[N_TOK * DIM];
__device__ float g_X[N_TOK * DIM];
__device__ float g_Y[N_TOK * DIM];
__device__ float g_bsum[8 * DIM];
__device__ int   g_K[N_TOK * KSHORT];

#define SWZ128(o) ((o) ^ (((o) >> 3) & 0x70))

// ---------------- mma.sync / ldmatrix helpers (sm_80+ PTX, no arch suffix) ---
__device__ __forceinline__ u32 smem_u32(const void* p) {
    u32 a;
    asm("{ .reg .u64 t; cvta.to.shared.u64 t, %1; cvt.u32.u64 %0, t; }" : "=r"(a) : "l"(p));
    return a;
}
__device__ __forceinline__ void ldsm4(u32* r, u32 addr) {
    asm volatile("ldmatrix.sync.aligned.m8n8.x4.shared.b16 {%0,%1,%2,%3}, [%4];"
        : "=r"(r[0]), "=r"(r[1]), "=r"(r[2]), "=r"(r[3]) : "r"(addr));
}
__device__ __forceinline__ void mma_bf16(float* c, const u32* a, u32 b0, u32 b1) {
    asm volatile("mma.sync.aligned.m16n8k16.row.col.f32.bf16.bf16.f32 "
        "{%0,%1,%2,%3}, {%4,%5,%6,%7}, {%8,%9}, {%0,%1,%2,%3};"
        : "+f"(c[0]), "+f"(c[1]), "+f"(c[2]), "+f"(c[3])
        : "r"(a[0]), "r"(a[1]), "r"(a[2]), "r"(a[3]), "r"(b0), "r"(b1));
}

// ---------------- embed gather (also emits bf16 copy for scores A) -----------
__global__ void k_embed(const int* __restrict__ tok, const float* __restrict__ tab,
                        float* __restrict__ E, __nv_bfloat16* __restrict__ E16) {
    int t = blockIdx.x, c = threadIdx.x;
    float v = tab[(size_t)tok[t] * DIM + c];
    E[t * DIM + c] = v;
    E16[t * DIM + c] = __float2bfloat16(v);
}

// ---------------- split builders: x -> (hi, lo) bf16, K-concat layouts -------
// Mcat row (768): [0:256)=hi, [256:512)=lo, [512:768)=hi
__global__ void k_split_m(const float* __restrict__ M, __nv_bfloat16* __restrict__ cat) {
    int row = blockIdx.x, c = threadIdx.x;
    float x = M[(size_t)row * DIM + c];
    __nv_bfloat16 hi = __float2bfloat16(x);
    __nv_bfloat16 lo = __float2bfloat16(x - __bfloat162float(hi));
    size_t base = (size_t)row * 768;
    cat[base + c] = hi;
    cat[base + 256 + c] = lo;
    cat[base + 512 + c] = hi;
}
// Ycat row (768): [0:256)=hi, [256:512)=hi, [512:768)=lo
__global__ void k_split_y(const float* __restrict__ Y, __nv_bfloat16* __restrict__ cat) {
    int row = blockIdx.x, c = threadIdx.x;
    float x = Y[(size_t)row * DIM + c];
    __nv_bfloat16 hi = __float2bfloat16(x);
    __nv_bfloat16 lo = __float2bfloat16(x - __bfloat162float(hi));
    size_t base = (size_t)row * 768;
    cat[base + c] = hi;
    cat[base + 256 + c] = hi;
    cat[base + 512 + c] = lo;
}

// ---------------- causal cumulative mean (2-phase) ----------------
__global__ void k_colsum(const float* __restrict__ E, float* __restrict__ bs) {
    int b = blockIdx.x, j = threadIdx.x;
    float s = 0.f;
    int base = b * 256;
#pragma unroll 4
    for (int r = 0; r < 256; r++) s += E[(base + r) * DIM + j];
    bs[b * DIM + j] = s;
}

__global__ void k_cummean(const float* __restrict__ E, const float* __restrict__ bs,
                          float* __restrict__ X) {
    int b = blockIdx.x, j = threadIdx.x;
    float acc = 0.f;
    for (int p = 0; p < b; p++) acc += bs[p * DIM + j];
    int base = b * 256;
    for (int r = 0; r < 256; r++) {
        int t = base + r;
        acc += E[t * DIM + j];
        X[t * DIM + j] = acc / (float)(t + 1);
    }
}

// ---------------- generic bf16 HMMA GEMM: C[row][col] = dot_K(A[row], B[col]) -
// 128x128 CTA tile, runtime K (multiple of 64) and row strides lda/ldb.
// OUTF32=0: bf16 out (scores, no guard). OUTF32=1: fp32 scalar out, col guard.
template <int OUTF32>
__global__ __launch_bounds__(256, 2) void k_hmma(
    const __nv_bfloat16* __restrict__ A,
    const __nv_bfloat16* __restrict__ B,
    int lda, int ldb, int K,
    __nv_bfloat16* __restrict__ Sout,
    float* __restrict__ Fout,
    int ncols)
{
    __shared__ __align__(16) char sA[128 * 128];  // rows [128][64 k] bf16, SW128
    __shared__ __align__(16) char sB[128 * 128];
    int tid = threadIdx.x;
    int w = tid >> 5, l = tid & 31;
    int wm = w & 3, wn = w >> 2;
    int rowBase = blockIdx.y * 128;
    int colBase = blockIdx.x * 128;

    float acc[2][8][4];
#pragma unroll
    for (int mi = 0; mi < 2; mi++)
#pragma unroll
        for (int ni = 0; ni < 8; ni++)
#pragma unroll
            for (int q = 0; q < 4; q++) acc[mi][ni][q] = 0.f;

    int a_row = wm * 32 + (l & 7) + ((l >> 3) & 1) * 8;   // + mi*16
    int a_kb  = ((l >> 4) * 8) * 2;                        // + ks*32
    int b_row = wn * 64 + (l & 7) + (l >> 4) * 8;          // + nj*16
    int b_kb  = (((l >> 3) & 1) * 8) * 2;                  // + ks*32

    u32 aBase = smem_u32(sA), bBase = smem_u32(sB);

    for (int kc = 0; kc < K; kc += 64) {
#pragma unroll
        for (int g = tid; g < 1024; g += 256) {
            int row = g >> 3, seg = g & 7;
            *(uint4*)(sA + SWZ128(row * 128 + seg * 16)) =
                *(const uint4*)(A + (size_t)(rowBase + row) * lda + kc + seg * 8);
        }
#pragma unroll
        for (int g = tid; g < 1024; g += 256) {
            int row = g >> 3, seg = g & 7;
            *(uint4*)(sB + SWZ128(row * 128 + seg * 16)) =
                *(const uint4*)(B + (size_t)(colBase + row) * ldb + kc + seg * 8);
        }
        __syncthreads();
#pragma unroll
        for (int ks = 0; ks < 4; ks++) {
            u32 a[2][4];
#pragma unroll
            for (int mi = 0; mi < 2; mi++)
                ldsm4(a[mi], aBase + SWZ128((a_row + mi * 16) * 128 + a_kb + ks * 32));
            u32 b[4][4];
#pragma unroll
            for (int nj = 0; nj < 4; nj++)
                ldsm4(b[nj], bBase + SWZ128((b_row + nj * 16) * 128 + b_kb + ks * 32));
#pragma unroll
            for (int mi = 0; mi < 2; mi++)
#pragma unroll
                for (int nj = 0; nj < 4; nj++) {
                    mma_bf16(acc[mi][nj * 2],     a[mi], b[nj][0], b[nj][1]);
                    mma_bf16(acc[mi][nj * 2 + 1], a[mi], b[nj][2], b[nj][3]);
                }
        }
        __syncthreads();
    }

    // epilogue: c0,c1 -> row l/4, cols (l%4)*2+{0,1}; c2,c3 -> row+8
#pragma unroll
    for (int mi = 0; mi < 2; mi++) {
        int r0 = rowBase + wm * 32 + mi * 16 + (l >> 2);
#pragma unroll
        for (int ni = 0; ni < 8; ni++) {
            int col = colBase + wn * 64 + ni * 8 + (l & 3) * 2;
            if (OUTF32) {
                if (col < ncols) {
                    Fout[(size_t)r0 * ncols + col]       = acc[mi][ni][0];
                    Fout[(size_t)(r0 + 8) * ncols + col] = acc[mi][ni][2];
                }
                if (col + 1 < ncols) {
                    Fout[(size_t)r0 * ncols + col + 1]       = acc[mi][ni][1];
                    Fout[(size_t)(r0 + 8) * ncols + col + 1] = acc[mi][ni][3];
                }
            } else {
                *(__nv_bfloat162*)&Sout[(size_t)r0 * ncols + col] =
                    __floats2bfloat162_rn(acc[mi][ni][0], acc[mi][ni][1]);
                *(__nv_bfloat162*)&Sout[(size_t)(r0 + 8) * ncols + col] =
                    __floats2bfloat162_rn(acc[mi][ni][2], acc[mi][ni][3]);
            }
        }
    }
}

// ---------------- top-128 superset + exact fp32 rescore + exact top-64 -------
__device__ __forceinline__ u32 ordf(float f) {
    u32 u = __float_as_uint(f);
    return (u & 0x80000000u) ? ~u : (u | 0x80000000u);
}
__device__ __forceinline__ u64 mk_key(float v, int idx) {
    return ((u64)ordf(v) << 32) | (u32)(65535 - idx);
}

__global__ __launch_bounds__(256) void k_topk_rescore(
    const __nv_bfloat16* __restrict__ S,
    const float* __restrict__ E,
    const float* __restrict__ Mm,
    int* __restrict__ Kset
) {
    __shared__ u64 cand[2048];
    __shared__ u64 tmax[256];
    __shared__ float Erow[256];
    __shared__ int cslot[128];
    __shared__ int cnt;
    int tid = threadIdx.x;
    int t = blockIdx.x;
    const __nv_bfloat16* row = S + (size_t)t * KMEM;
    Erow[tid] = E[t * DIM + tid];
    if (tid == 0) cnt = 0;

    u64 mk = 0ull;
#pragma unroll 8
    for (int i = 0; i < 256; i++) {
        int idx = tid + (i << 8);
        u64 key = mk_key(__bfloat162float(row[idx]), idx);
        if (key > mk) mk = key;
    }
    tmax[tid] = mk;
    __syncthreads();

    for (int k = 2; k <= 256; k <<= 1) {
        for (int j = k >> 1; j > 0; j >>= 1) {
            int ix = tid ^ j;
            if (ix > tid) {
                u64 a = tmax[tid], b = tmax[ix];
                bool up = ((tid & k) == 0);
                if (up ? (a < b) : (a > b)) { tmax[tid] = b; tmax[ix] = a; }
            }
            __syncthreads();
        }
    }
    u64 tau = tmax[127];   // >=128 keys >= tau -> approx top-128 subset
    __syncthreads();

#pragma unroll 4
    for (int i = 0; i < 256; i++) {
        int idx = tid + (i << 8);
        u64 key = mk_key(__bfloat162float(row[idx]), idx);
        if (key >= tau) {
            int p = atomicAdd(&cnt, 1);
            if (p < 2048) cand[p] = key;
        }
    }
    __syncthreads();
    int c = cnt; if (c > 2048) c = 2048;
    for (int e = c + tid; e < 2048; e += 256) cand[e] = 0ull;
    __syncthreads();
    for (int k = 2; k <= 2048; k <<= 1) {
        for (int j = k >> 1; j > 0; j >>= 1) {
            for (int e = tid; e < 2048; e += 256) {
                int ix = e ^ j;
                if (ix > e) {
                    u64 a = cand[e], b = cand[ix];
                    bool up = ((e & k) == 0);
                    if (up ? (a < b) : (a > b)) { cand[e] = b; cand[ix] = a; }
                }
            }
            __syncthreads();
        }
    }
    if (tid < 128) cslot[tid] = 65535 - (int)(cand[tid] & 0xFFFFull);
    __syncthreads();

    // exact fp32 rescore of 128 candidates (true top-64 provably inside)
    {
        int w = tid >> 5, l = tid & 31;
        for (int j = 0; j < 16; j++) {
            int ci = w * 16 + j;
            int slot = cslot[ci];
            const float* mrow = &Mm[(size_t)slot * DIM];
            float p = 0.f;
#pragma unroll
            for (int i = 0; i < 8; i++) p = fmaf(Erow[l + 32 * i], mrow[l + 32 * i], p);
#pragma unroll
            for (int o = 16; o > 0; o >>= 1) p += __shfl_xor_sync(0xffffffffu, p, o);
            if (l == 0) tmax[ci] = mk_key(p, slot);
        }
    }
    if (tid >= 128) tmax[tid] = 0ull;
    __syncthreads();

    for (int k = 2; k <= 256; k <<= 1) {
        for (int j = k >> 1; j > 0; j >>= 1) {
            int ix = tid ^ j;
            if (ix > tid) {
                u64 a = tmax[tid], b = tmax[ix];
                bool up = ((tid & k) == 0);
                if (up ? (a < b) : (a > b)) { tmax[tid] = b; tmax[ix] = a; }
            }
            __syncthreads();
        }
    }
    if (tid < 64) Kset[t * 64 + tid] = 65535 - (int)(tmax[tid] & 0xFFFFull);
}

// ---------------- solver: 4 ADMM/mirror-descent steps per token ----------------
#define SLV_FLOATS (64 * 257 + 256 * 17 + 256 + 256 + 64 + 64 + 4 * 64 + 2 + 64)
#define SLV_BYTES  (SLV_FLOATS * 4)

__global__ __launch_bounds__(256) void k_solver(const float* __restrict__ X,
                                                const float* __restrict__ M,
                                                const float* __restrict__ A,
                                                const int* __restrict__ Kidx,
                                                float* __restrict__ Yout) {
    extern __shared__ float sm[];
    float* Mg   = sm;                 // [64][257]
    float* band = Mg + 64 * 257;      // [256][17]
    float* Ysm  = band + 256 * 17;    // [256]
    float* vsm  = Ysm + 256;          // [256]
    float* Psm  = vsm + 256;          // [64]
    float* Lsm  = Psm + 64;           // [64]
    float* gp   = Lsm + 64;           // [4][64]
    float* red  = gp + 256;           // [2]
    int*   sidx = (int*)(red + 2);    // [64]

    int tid = threadIdx.x;
    int t = blockIdx.x;
    if (tid < 64) sidx[tid] = Kidx[t * 64 + tid];
    __syncthreads();
    for (int r = 0; r < 64; r++)
        Mg[r * 257 + tid] = M[(size_t)sidx[r] * DIM + tid];
    {
        int j = tid;
#pragma unroll
        for (int o = 0; o < 17; o++) {
            int i = j - 8 + o;
            band[j * 17 + o] = (i >= 0 && i < 256) ? A[j * 256 + i] : 0.f;
        }
    }
    float xr = X[t * DIM + tid];
    if (tid < 64) Psm[tid] = 1.0f / 64.0f;
    __syncthreads();
    {
        float y0 = 0.f;
        for (int k = 0; k < 64; k++) y0 = fmaf(Psm[k], Mg[k * 257 + tid], y0);
        Ysm[tid] = y0;
    }
    float lam = 0.f;
    __syncthreads();

    for (int step = 0; step < 4; step++) {
        float ymp = 0.f;
#pragma unroll 8
        for (int k = 0; k < 64; k++) ymp = fmaf(Psm[k], Mg[k * 257 + tid], ymp);
        float yold = Ysm[tid];
        float r_ = yold - ymp;
        lam = fmaf(RHO_C, r_, lam);
        float yab = 0.f;
#pragma unroll
        for (int o = 0; o < 17; o++) {
            int i = tid - 8 + o;
            if (i >= 0 && i < 256) yab = fmaf(band[tid * 17 + o], Ysm[i], yab);
        }
        float gY = yab - xr + lam + RHO_C * r_;
        float ynew = yold - TAU_C * gY;
        __syncthreads();
        Ysm[tid] = ynew;
        vsm[tid] = RHO_C * (ynew - ymp) + lam;
        __syncthreads();
        {
            int k = tid & 63, part = tid >> 6;
            const float* vv = vsm + part * 64;
            const float* mm = Mg + k * 257 + part * 64;
            float p_ = 0.f;
#pragma unroll 8
            for (int jj = 0; jj < 64; jj++) p_ = fmaf(vv[jj], mm[jj], p_);
            gp[part * 64 + k] = p_;
        }
        __syncthreads();
        if (tid < 64) {
            float gPk = -(gp[tid] + gp[64 + tid] + gp[128 + tid] + gp[192 + tid]);
            Lsm[tid] = logf(Psm[tid] + 1e-20f) - ETA_C * gPk;
        }
        __syncthreads();
        if (tid < 32) {
            float m_ = fmaxf(Lsm[tid], Lsm[tid + 32]);
            for (int o = 16; o > 0; o >>= 1) m_ = fmaxf(m_, __shfl_xor_sync(0xffffffffu, m_, o));
            if (tid == 0) red[0] = m_;
        }
        __syncthreads();
        if (tid < 64) Psm[tid] = expf(Lsm[tid] - red[0]);
        __syncthreads();
        if (tid < 32) {
            float s_ = Psm[tid] + Psm[tid + 32];
            for (int o = 16; o > 0; o >>= 1) s_ += __shfl_xor_sync(0xffffffffu, s_, o);
            if (tid == 0) red[1] = s_;
        }
        __syncthreads();
        if (tid < 64) Psm[tid] = Psm[tid] / red[1];
        __syncthreads();
    }
    Yout[t * DIM + tid] = Ysm[tid];
}

// ---------------- launcher ----------------
extern "C" void kernel_launch(void* const* d_in, const int* in_sizes, int n_in,
                              void* d_out, int out_size) {
    const int*   tokens = (const int*)d_in[0];
    const float* tab    = (const float*)d_in[1];
    const float* M      = (const float*)d_in[2];
    const float* A      = (const float*)d_in[3];
    float* out = (float*)d_out;

    __nv_bfloat16 *pS, *pMcat, *pYcat, *pE16;
    float *pE, *pX, *pY, *pB; int* pK;
    cudaGetSymbolAddress((void**)&pS, g_S16);
    cudaGetSymbolAddress((void**)&pMcat, g_Mcat);
    cudaGetSymbolAddress((void**)&pYcat, g_Ycat);
    cudaGetSymbolAddress((void**)&pE16, g_E16);
    cudaGetSymbolAddress((void**)&pE, g_E);
    cudaGetSymbolAddress((void**)&pX, g_X);
    cudaGetSymbolAddress((void**)&pY, g_Y);
    cudaGetSymbolAddress((void**)&pB, g_bsum);
    cudaGetSymbolAddress((void**)&pK, g_K);

    k_embed<<<N_TOK, 256>>>(tokens, tab, pE, pE16);
    k_colsum<<<8, 256>>>(pE, pB);
    k_cummean<<<8, 256>>>(pE, pB, pX);
    k_split_m<<<KMEM, 256>>>(M, pMcat);   // [Whi|Wlo|Whi], hi also feeds scores

    // approx scores: bf16 HMMA, K=256 (cols 0..255 of Mcat = Whi)
    dim3 gs(KMEM / 128, N_TOK / 128);
    k_hmma<0><<<gs, 256>>>(pE16, pMcat, DIM, 768, 256, pS, nullptr, KMEM);

    // superset top-128 -> exact fp32 rescore -> exact top-64
    k_topk_rescore<<<N_TOK, 256>>>(pS, pE, M, pK);

    cudaFuncSetAttribute(k_solver, cudaFuncAttributeMaxDynamicSharedMemorySize, SLV_BYTES);
    k_solver<<<N_TOK, 256, SLV_BYTES>>>(pX, M, A, pK, pY);

    // logits: split-bf16 HMMA, single K=768 GEMM = Yhi.Whi + Yhi.Wlo + Ylo.Whi
    k_split_y<<<N_TOK, 256>>>(pY, pYcat);
    dim3 gl((VOCAB + 127) / 128, N_TOK / 128);
    k_hmma<1><<<gl, 256>>>(pYcat, pMcat, 768, 768, 768, nullptr, out, VOCAB);
}

// round 12
// speedup vs baseline: 2.9220x; 1.4269x over previous
#include <cuda_runtime.h>
#include <cuda_fp16.h>
#include <cstdint>

#define N_TOK   2048
#define DIM     256
#define KMEM    65536
#define KSHORT  64
#define VOCAB   50257
#define RHO_C   1.0f
#define TAU_C   0.1f
#define ETA_C   0.1f

typedef unsigned long long u64;
typedef unsigned int u32;

// ---------------- scratch (static __device__ — no allocation) ----------------
__device__ __align__(16) __half g_Sh[(size_t)N_TOK * KMEM];   // 256 MB approx scores
__device__ __align__(16) __half g_Mh[(size_t)KMEM * DIM];     // 32 MB fp16 memory bank
__device__ __align__(16) __half g_Eh[N_TOK * DIM];
__device__ __align__(16) __half g_Yh[N_TOK * DIM];
__device__ float g_E[N_TOK * DIM];
__device__ float g_X[N_TOK * DIM];
__device__ float g_Y[N_TOK * DIM];
__device__ float g_bsum[8 * DIM];
__device__ int   g_K[N_TOK * KSHORT];

#define SWZ128(o) ((o) ^ (((o) >> 3) & 0x70))

// ---------------- PTX helpers (all sm_80-era, safe for compute_103) ----------
__device__ __forceinline__ u32 smem_u32(const void* p) {
    u32 a;
    asm("{ .reg .u64 t; cvta.to.shared.u64 t, %1; cvt.u32.u64 %0, t; }" : "=r"(a) : "l"(p));
    return a;
}
__device__ __forceinline__ void ldsm4(u32* r, u32 addr) {
    asm volatile("ldmatrix.sync.aligned.m8n8.x4.shared.b16 {%0,%1,%2,%3}, [%4];"
        : "=r"(r[0]), "=r"(r[1]), "=r"(r[2]), "=r"(r[3]) : "r"(addr));
}
__device__ __forceinline__ void mma_f16(float* c, const u32* a, u32 b0, u32 b1) {
    asm volatile("mma.sync.aligned.m16n8k16.row.col.f32.f16.f16.f32 "
        "{%0,%1,%2,%3}, {%4,%5,%6,%7}, {%8,%9}, {%0,%1,%2,%3};"
        : "+f"(c[0]), "+f"(c[1]), "+f"(c[2]), "+f"(c[3])
        : "r"(a[0]), "r"(a[1]), "r"(a[2]), "r"(a[3]), "r"(b0), "r"(b1));
}
__device__ __forceinline__ void cp16(u32 dst, const void* src) {
    asm volatile("cp.async.cg.shared.global [%0], [%1], 16;" :: "r"(dst), "l"(src));
}
__device__ __forceinline__ void cp_commit() { asm volatile("cp.async.commit_group;"); }
template <int N>
__device__ __forceinline__ void cp_wait() { asm volatile("cp.async.wait_group %0;" :: "n"(N)); }

// ---------------- embed gather (fp32 + fp16 copies) ----------------
__global__ void k_embed(const int* __restrict__ tok, const float* __restrict__ tab,
                        float* __restrict__ E, __half* __restrict__ Eh) {
    int t = blockIdx.x, c = threadIdx.x;
    float v = tab[(size_t)tok[t] * DIM + c];
    E[t * DIM + c] = v;
    Eh[t * DIM + c] = __float2half(v);
}

// ---------------- fp32 -> fp16 bulk convert ----------------
__global__ void k_cvt_h(const float* __restrict__ src, __half* __restrict__ dst, int n4) {
    int i = blockIdx.x * 256 + threadIdx.x;
    if (i < n4) {
        float4 v = ((const float4*)src)[i];
        ((__half2*)dst)[2 * i]     = __floats2half2_rn(v.x, v.y);
        ((__half2*)dst)[2 * i + 1] = __floats2half2_rn(v.z, v.w);
    }
}

// ---------------- causal cumulative mean (2-phase) ----------------
__global__ void k_colsum(const float* __restrict__ E, float* __restrict__ bs) {
    int b = blockIdx.x, j = threadIdx.x;
    float s = 0.f;
    int base = b * 256;
#pragma unroll 4
    for (int r = 0; r < 256; r++) s += E[(base + r) * DIM + j];
    bs[b * DIM + j] = s;
}

__global__ void k_cummean(const float* __restrict__ E, const float* __restrict__ bs,
                          float* __restrict__ X) {
    int b = blockIdx.x, j = threadIdx.x;
    float acc = 0.f;
    for (int p = 0; p < b; p++) acc += bs[p * DIM + j];
    int base = b * 256;
    for (int r = 0; r < 256; r++) {
        int t = base + r;
        acc += E[t * DIM + j];
        X[t * DIM + j] = acc / (float)(t + 1);
    }
}

// ---------------- fp16 HMMA GEMM, cp.async double-buffered ----------------
// C[row][col] = dot_256(A[row], B[col]); 128x128 CTA tile, K=256 (4 chunks).
// OUTF32=0: half out (scores). OUTF32=1: fp32 scalar out, col guard (logits).
// dyn smem: sA[2] 16KB + sB[2] 16KB = 64KB.
template <int OUTF32>
__global__ __launch_bounds__(256, 2) void k_hmma(
    const __half* __restrict__ A,
    const __half* __restrict__ B,
    __half* __restrict__ Sout,
    float* __restrict__ Fout,
    int ncols)
{
    extern __shared__ char smem[];
    u32 aAddr[2] = { smem_u32(smem),         smem_u32(smem + 16384) };
    u32 bAddr[2] = { smem_u32(smem + 32768), smem_u32(smem + 49152) };
    int tid = threadIdx.x;
    int w = tid >> 5, l = tid & 31;
    int wm = w & 3, wn = w >> 2;
    int rowBase = blockIdx.y * 128;
    int colBase = blockIdx.x * 128;

    float acc[2][8][4];
#pragma unroll
    for (int mi = 0; mi < 2; mi++)
#pragma unroll
        for (int ni = 0; ni < 8; ni++)
#pragma unroll
            for (int q = 0; q < 4; q++) acc[mi][ni][q] = 0.f;

    int a_row = wm * 32 + (l & 7) + ((l >> 3) & 1) * 8;   // + mi*16
    int a_kb  = ((l >> 4) * 8) * 2;                        // + ks*32
    int b_row = wn * 64 + (l & 7) + (l >> 4) * 8;          // + nj*16
    int b_kb  = (((l >> 3) & 1) * 8) * 2;                  // + ks*32

    // prologue: async-load chunk 0 into stage 0
#pragma unroll
    for (int g = tid; g < 1024; g += 256) {
        int row = g >> 3, seg = g & 7;
        cp16(aAddr[0] + SWZ128(row * 128 + seg * 16),
             A + (size_t)(rowBase + row) * DIM + seg * 8);
    }
#pragma unroll
    for (int g = tid; g < 1024; g += 256) {
        int row = g >> 3, seg = g & 7;
        cp16(bAddr[0] + SWZ128(row * 128 + seg * 16),
             B + (size_t)(colBase + row) * DIM + seg * 8);
    }
    cp_commit();

#pragma unroll
    for (int i = 0; i < 4; i++) {
        int s = i & 1;
        if (i + 1 < 4) {
            int kc = (i + 1) << 6, sn = (i + 1) & 1;
#pragma unroll
            for (int g = tid; g < 1024; g += 256) {
                int row = g >> 3, seg = g & 7;
                cp16(aAddr[sn] + SWZ128(row * 128 + seg * 16),
                     A + (size_t)(rowBase + row) * DIM + kc + seg * 8);
            }
#pragma unroll
            for (int g = tid; g < 1024; g += 256) {
                int row = g >> 3, seg = g & 7;
                cp16(bAddr[sn] + SWZ128(row * 128 + seg * 16),
                     B + (size_t)(colBase + row) * DIM + kc + seg * 8);
            }
            cp_commit();
            cp_wait<1>();      // stage i resident; stage i+1 may be in flight
        } else {
            cp_wait<0>();
        }
        __syncthreads();
#pragma unroll
        for (int ks = 0; ks < 4; ks++) {
            u32 a[2][4];
#pragma unroll
            for (int mi = 0; mi < 2; mi++)
                ldsm4(a[mi], aAddr[s] + SWZ128((a_row + mi * 16) * 128 + a_kb + ks * 32));
            u32 b[4][4];
#pragma unroll
            for (int nj = 0; nj < 4; nj++)
                ldsm4(b[nj], bAddr[s] + SWZ128((b_row + nj * 16) * 128 + b_kb + ks * 32));
#pragma unroll
            for (int mi = 0; mi < 2; mi++)
#pragma unroll
                for (int nj = 0; nj < 4; nj++) {
                    mma_f16(acc[mi][nj * 2],     a[mi], b[nj][0], b[nj][1]);
                    mma_f16(acc[mi][nj * 2 + 1], a[mi], b[nj][2], b[nj][3]);
                }
        }
        __syncthreads();       // all warps done with stage s before it is refilled
    }

    // epilogue: c0,c1 -> row l/4, cols (l%4)*2+{0,1}; c2,c3 -> row+8
#pragma unroll
    for (int mi = 0; mi < 2; mi++) {
        int r0 = rowBase + wm * 32 + mi * 16 + (l >> 2);
#pragma unroll
        for (int ni = 0; ni < 8; ni++) {
            int col = colBase + wn * 64 + ni * 8 + (l & 3) * 2;
            if (OUTF32) {
                if (col < ncols) {
                    Fout[(size_t)r0 * ncols + col]       = acc[mi][ni][0];
                    Fout[(size_t)(r0 + 8) * ncols + col] = acc[mi][ni][2];
                }
                if (col + 1 < ncols) {
                    Fout[(size_t)r0 * ncols + col + 1]       = acc[mi][ni][1];
                    Fout[(size_t)(r0 + 8) * ncols + col + 1] = acc[mi][ni][3];
                }
            } else {
                *(__half2*)&Sout[(size_t)r0 * ncols + col] =
                    __floats2half2_rn(acc[mi][ni][0], acc[mi][ni][1]);
                *(__half2*)&Sout[(size_t)(r0 + 8) * ncols + col] =
                    __floats2half2_rn(acc[mi][ni][2], acc[mi][ni][3]);
            }
        }
    }
}

// ---------------- top-128 superset + exact fp32 rescore + exact top-64 -------
__device__ __forceinline__ u32 ordf(float f) {
    u32 u = __float_as_uint(f);
    return (u & 0x80000000u) ? ~u : (u | 0x80000000u);
}
__device__ __forceinline__ u64 mk_key(float v, int idx) {
    return ((u64)ordf(v) << 32) | (u32)(65535 - idx);
}

__global__ __launch_bounds__(256) void k_topk_rescore(
    const __half* __restrict__ S,
    const float* __restrict__ E,
    const float* __restrict__ Mm,
    int* __restrict__ Kset
) {
    __shared__ u64 cand[2048];
    __shared__ u64 tmax[256];
    __shared__ float Erow[256];
    __shared__ int cslot[128];
    __shared__ int cnt;
    int tid = threadIdx.x;
    int t = blockIdx.x;
    const __half2* row2 = (const __half2*)(S + (size_t)t * KMEM);
    Erow[tid] = E[t * DIM + tid];
    if (tid == 0) cnt = 0;

    // pass 1: per-thread strip max (vectorized half2, coalesced)
    u64 mk = 0ull;
#pragma unroll 8
    for (int i = 0; i < 128; i++) {
        int j = tid + (i << 8);
        __half2 h = row2[j];
        u64 k0 = mk_key(__low2float(h), 2 * j);
        u64 k1 = mk_key(__high2float(h), 2 * j + 1);
        if (k0 > mk) mk = k0;
        if (k1 > mk) mk = k1;
    }
    tmax[tid] = mk;
    __syncthreads();

    // bitonic sort 256 strip maxima, descending
    for (int k = 2; k <= 256; k <<= 1) {
        for (int j = k >> 1; j > 0; j >>= 1) {
            int ix = tid ^ j;
            if (ix > tid) {
                u64 a = tmax[tid], b = tmax[ix];
                bool up = ((tid & k) == 0);
                if (up ? (a < b) : (a > b)) { tmax[tid] = b; tmax[ix] = a; }
            }
            __syncthreads();
        }
    }
    u64 tau = tmax[127];   // >=128 keys >= tau -> approx top-128 is a subset
    __syncthreads();

    // pass 2: collect keys >= tau
#pragma unroll 4
    for (int i = 0; i < 128; i++) {
        int j = tid + (i << 8);
        __half2 h = row2[j];
        u64 k0 = mk_key(__low2float(h), 2 * j);
        u64 k1 = mk_key(__high2float(h), 2 * j + 1);
        if (k0 >= tau) { int p = atomicAdd(&cnt, 1); if (p < 2048) cand[p] = k0; }
        if (k1 >= tau) { int p = atomicAdd(&cnt, 1); if (p < 2048) cand[p] = k1; }
    }
    __syncthreads();
    int c = cnt; if (c > 2048) c = 2048;
    for (int e = c + tid; e < 2048; e += 256) cand[e] = 0ull;
    __syncthreads();
    for (int k = 2; k <= 2048; k <<= 1) {
        for (int j = k >> 1; j > 0; j >>= 1) {
            for (int e = tid; e < 2048; e += 256) {
                int ix = e ^ j;
                if (ix > e) {
                    u64 a = cand[e], b = cand[ix];
                    bool up = ((e & k) == 0);
                    if (up ? (a < b) : (a > b)) { cand[e] = b; cand[ix] = a; }
                }
            }
            __syncthreads();
        }
    }
    if (tid < 128) cslot[tid] = 65535 - (int)(cand[tid] & 0xFFFFull);
    __syncthreads();

    // exact fp32 rescore of 128 candidates (true top-64 provably inside:
    // fp16 approx sigma ~1.6e-5 vs top64->128 margin ~1.9e-3)
    {
        int w = tid >> 5, l = tid & 31;
        for (int j = 0; j < 16; j++) {
            int ci = w * 16 + j;
            int slot = cslot[ci];
            const float* mrow = &Mm[(size_t)slot * DIM];
            float p = 0.f;
#pragma unroll
            for (int i = 0; i < 8; i++) p = fmaf(Erow[l + 32 * i], mrow[l + 32 * i], p);
#pragma unroll
            for (int o = 16; o > 0; o >>= 1) p += __shfl_xor_sync(0xffffffffu, p, o);
            if (l == 0) tmax[ci] = mk_key(p, slot);
        }
    }
    if (tid >= 128) tmax[tid] = 0ull;
    __syncthreads();

    for (int k = 2; k <= 256; k <<= 1) {
        for (int j = k >> 1; j > 0; j >>= 1) {
            int ix = tid ^ j;
            if (ix > tid) {
                u64 a = tmax[tid], b = tmax[ix];
                bool up = ((tid & k) == 0);
                if (up ? (a < b) : (a > b)) { tmax[tid] = b; tmax[ix] = a; }
            }
            __syncthreads();
        }
    }
    if (tid < 64) Kset[t * 64 + tid] = 65535 - (int)(tmax[tid] & 0xFFFFull);
}

// ---------------- solver: 4 ADMM/mirror-descent steps per token ----------------
#define SLV_FLOATS (64 * 257 + 256 * 17 + 256 + 256 + 64 + 64 + 4 * 64 + 2 + 64)
#define SLV_BYTES  (SLV_FLOATS * 4)

__global__ __launch_bounds__(256) void k_solver(const float* __restrict__ X,
                                                const float* __restrict__ M,
                                                const float* __restrict__ A,
                                                const int* __restrict__ Kidx,
                                                float* __restrict__ Yout,
                                                __half* __restrict__ Yh) {
    extern __shared__ float sm[];
    float* Mg   = sm;                 // [64][257]
    float* band = Mg + 64 * 257;      // [256][17]
    float* Ysm  = band + 256 * 17;    // [256]
    float* vsm  = Ysm + 256;          // [256]
    float* Psm  = vsm + 256;          // [64]
    float* Lsm  = Psm + 64;           // [64]
    float* gp   = Lsm + 64;           // [4][64]
    float* red  = gp + 256;           // [2]
    int*   sidx = (int*)(red + 2);    // [64]

    int tid = threadIdx.x;
    int t = blockIdx.x;
    if (tid < 64) sidx[tid] = Kidx[t * 64 + tid];
    __syncthreads();
    for (int r = 0; r < 64; r++)
        Mg[r * 257 + tid] = M[(size_t)sidx[r] * DIM + tid];
    {
        int j = tid;
#pragma unroll
        for (int o = 0; o < 17; o++) {
            int i = j - 8 + o;
            band[j * 17 + o] = (i >= 0 && i < 256) ? A[j * 256 + i] : 0.f;
        }
    }
    float xr = X[t * DIM + tid];
    if (tid < 64) Psm[tid] = 1.0f / 64.0f;
    __syncthreads();
    {
        float y0 = 0.f;
        for (int k = 0; k < 64; k++) y0 = fmaf(Psm[k], Mg[k * 257 + tid], y0);
        Ysm[tid] = y0;
    }
    float lam = 0.f;
    __syncthreads();

    for (int step = 0; step < 4; step++) {
        float ymp = 0.f;
#pragma unroll 8
        for (int k = 0; k < 64; k++) ymp = fmaf(Psm[k], Mg[k * 257 + tid], ymp);
        float yold = Ysm[tid];
        float r_ = yold - ymp;
        lam = fmaf(RHO_C, r_, lam);
        float yab = 0.f;
#pragma unroll
        for (int o = 0; o < 17; o++) {
            int i = tid - 8 + o;
            if (i >= 0 && i < 256) yab = fmaf(band[tid * 17 + o], Ysm[i], yab);
        }
        float gY = yab - xr + lam + RHO_C * r_;
        float ynew = yold - TAU_C * gY;
        __syncthreads();
        Ysm[tid] = ynew;
        vsm[tid] = RHO_C * (ynew - ymp) + lam;
        __syncthreads();
        {
            int k = tid & 63, part = tid >> 6;
            const float* vv = vsm + part * 64;
            const float* mm = Mg + k * 257 + part * 64;
            float p_ = 0.f;
#pragma unroll 8
            for (int jj = 0; jj < 64; jj++) p_ = fmaf(vv[jj], mm[jj], p_);
            gp[part * 64 + k] = p_;
        }
        __syncthreads();
        if (tid < 64) {
            float gPk = -(gp[tid] + gp[64 + tid] + gp[128 + tid] + gp[192 + tid]);
            Lsm[tid] = logf(Psm[tid] + 1e-20f) - ETA_C * gPk;
        }
        __syncthreads();
        if (tid < 32) {
            float m_ = fmaxf(Lsm[tid], Lsm[tid + 32]);
            for (int o = 16; o > 0; o >>= 1) m_ = fmaxf(m_, __shfl_xor_sync(0xffffffffu, m_, o));
            if (tid == 0) red[0] = m_;
        }
        __syncthreads();
        if (tid < 64) Psm[tid] = expf(Lsm[tid] - red[0]);
        __syncthreads();
        if (tid < 32) {
            float s_ = Psm[tid] + Psm[tid + 32];
            for (int o = 16; o > 0; o >>= 1) s_ += __shfl_xor_sync(0xffffffffu, s_, o);
            if (tid == 0) red[1] = s_;
        }
        __syncthreads();
        if (tid < 64) Psm[tid] = Psm[tid] / red[1];
        __syncthreads();
    }
    float yfin = Ysm[tid];
    Yout[t * DIM + tid] = yfin;
    Yh[t * DIM + tid] = __float2half(yfin);
}

// ---------------- launcher ----------------
extern "C" void kernel_launch(void* const* d_in, const int* in_sizes, int n_in,
                              void* d_out, int out_size) {
    const int*   tokens = (const int*)d_in[0];
    const float* tab    = (const float*)d_in[1];
    const float* M      = (const float*)d_in[2];
    const float* A      = (const float*)d_in[3];
    float* out = (float*)d_out;

    __half *pSh, *pMh, *pEh, *pYh;
    float *pE, *pX, *pY, *pB; int* pK;
    cudaGetSymbolAddress((void**)&pSh, g_Sh);
    cudaGetSymbolAddress((void**)&pMh, g_Mh);
    cudaGetSymbolAddress((void**)&pEh, g_Eh);
    cudaGetSymbolAddress((void**)&pYh, g_Yh);
    cudaGetSymbolAddress((void**)&pE, g_E);
    cudaGetSymbolAddress((void**)&pX, g_X);
    cudaGetSymbolAddress((void**)&pY, g_Y);
    cudaGetSymbolAddress((void**)&pB, g_bsum);
    cudaGetSymbolAddress((void**)&pK, g_K);

    k_embed<<<N_TOK, 256>>>(tokens, tab, pE, pEh);
    k_colsum<<<8, 256>>>(pE, pB);
    k_cummean<<<8, 256>>>(pE, pB, pX);
    k_cvt_h<<<(KMEM * DIM / 4 + 255) / 256, 256>>>(M, pMh, KMEM * DIM / 4);

    // approx scores: fp16 HMMA, cp.async double-buffered, K=256
    cudaFuncSetAttribute(k_hmma<0>, cudaFuncAttributeMaxDynamicSharedMemorySize, 65536);
    cudaFuncSetAttribute(k_hmma<1>, cudaFuncAttributeMaxDynamicSharedMemorySize, 65536);
    dim3 gs(KMEM / 128, N_TOK / 128);
    k_hmma<0><<<gs, 256, 65536>>>(pEh, pMh, pSh, nullptr, KMEM);

    // superset top-128 -> exact fp32 rescore -> exact top-64
    k_topk_rescore<<<N_TOK, 256>>>(pSh, pE, M, pK);

    cudaFuncSetAttribute(k_solver, cudaFuncAttributeMaxDynamicSharedMemorySize, SLV_BYTES);
    k_solver<<<N_TOK, 256, SLV_BYTES>>>(pX, M, A, pK, pY, pYh);

    // logits: single fp16 HMMA (error ~3.5e-4 << 1e-3), K=256
    dim3 gl((VOCAB + 127) / 128, N_TOK / 128);
    k_hmma<1><<<gl, 256, 65536>>>(pYh, pMh, nullptr, out, VOCAB);
}

// round 13
// speedup vs baseline: 3.3868x; 1.1591x over previous
#include <cuda_runtime.h>
#include <cuda_fp16.h>
#include <cstdint>

#define N_TOK   2048
#define DIM     256
#define KMEM    65536
#define KSHORT  64
#define VOCAB   50257
#define RHO_C   1.0f
#define TAU_C   0.1f
#define ETA_C   0.1f

typedef unsigned long long u64;
typedef unsigned int u32;

// ---------------- scratch (static __device__ — no allocation) ----------------
__device__ __align__(16) __half g_Sh[(size_t)N_TOK * KMEM];   // 256 MB approx scores
__device__ __align__(16) __half g_Mh[(size_t)KMEM * DIM];     // 32 MB fp16 memory bank
__device__ __align__(16) __half g_Eh[N_TOK * DIM];
__device__ __align__(16) __half g_Yh[N_TOK * DIM];
__device__ u64   g_Gmax[(size_t)N_TOK * 512];                 // 8 MB strip maxima
__device__ float g_E[N_TOK * DIM];
__device__ float g_X[N_TOK * DIM];
__device__ float g_Y[N_TOK * DIM];
__device__ float g_bsum[8 * DIM];
__device__ int   g_K[N_TOK * KSHORT];

#define SWZ128(o) ((o) ^ (((o) >> 3) & 0x70))
#define SMEM_BYTES 69632   // 64KB pipeline stages, reused as 128x132 fp32 stage + rowmax

// ---------------- PTX helpers (all sm_80-era, safe for compute_103) ----------
__device__ __forceinline__ u32 smem_u32(const void* p) {
    u32 a;
    asm("{ .reg .u64 t; cvta.to.shared.u64 t, %1; cvt.u32.u64 %0, t; }" : "=r"(a) : "l"(p));
    return a;
}
__device__ __forceinline__ void ldsm4(u32* r, u32 addr) {
    asm volatile("ldmatrix.sync.aligned.m8n8.x4.shared.b16 {%0,%1,%2,%3}, [%4];"
        : "=r"(r[0]), "=r"(r[1]), "=r"(r[2]), "=r"(r[3]) : "r"(addr));
}
__device__ __forceinline__ void mma_f16(float* c, const u32* a, u32 b0, u32 b1) {
    asm volatile("mma.sync.aligned.m16n8k16.row.col.f32.f16.f16.f32 "
        "{%0,%1,%2,%3}, {%4,%5,%6,%7}, {%8,%9}, {%0,%1,%2,%3};"
        : "+f"(c[0]), "+f"(c[1]), "+f"(c[2]), "+f"(c[3])
        : "r"(a[0]), "r"(a[1]), "r"(a[2]), "r"(a[3]), "r"(b0), "r"(b1));
}
__device__ __forceinline__ void cp16(u32 dst, const void* src) {
    asm volatile("cp.async.cg.shared.global [%0], [%1], 16;" :: "r"(dst), "l"(src));
}
__device__ __forceinline__ void cp_commit() { asm volatile("cp.async.commit_group;"); }
template <int N>
__device__ __forceinline__ void cp_wait() { asm volatile("cp.async.wait_group %0;" :: "n"(N)); }

__device__ __forceinline__ u32 ordf(float f) {
    u32 u = __float_as_uint(f);
    return (u & 0x80000000u) ? ~u : (u | 0x80000000u);
}
__device__ __forceinline__ u64 mk_key(float v, int idx) {
    return ((u64)ordf(v) << 32) | (u32)(65535 - idx);
}

// ---------------- embed gather (fp32 + fp16 copies) ----------------
__global__ void k_embed(const int* __restrict__ tok, const float* __restrict__ tab,
                        float* __restrict__ E, __half* __restrict__ Eh) {
    int t = blockIdx.x, c = threadIdx.x;
    float v = tab[(size_t)tok[t] * DIM + c];
    E[t * DIM + c] = v;
    Eh[t * DIM + c] = __float2half(v);
}

// ---------------- fp32 -> fp16 bulk convert ----------------
__global__ void k_cvt_h(const float* __restrict__ src, __half* __restrict__ dst, int n4) {
    int i = blockIdx.x * 256 + threadIdx.x;
    if (i < n4) {
        float4 v = ((const float4*)src)[i];
        ((__half2*)dst)[2 * i]     = __floats2half2_rn(v.x, v.y);
        ((__half2*)dst)[2 * i + 1] = __floats2half2_rn(v.z, v.w);
    }
}

// ---------------- causal cumulative mean (2-phase) ----------------
__global__ void k_colsum(const float* __restrict__ E, float* __restrict__ bs) {
    int b = blockIdx.x, j = threadIdx.x;
    float s = 0.f;
    int base = b * 256;
#pragma unroll 4
    for (int r = 0; r < 256; r++) s += E[(base + r) * DIM + j];
    bs[b * DIM + j] = s;
}

__global__ void k_cummean(const float* __restrict__ E, const float* __restrict__ bs,
                          float* __restrict__ X) {
    int b = blockIdx.x, j = threadIdx.x;
    float acc = 0.f;
    for (int p = 0; p < b; p++) acc += bs[p * DIM + j];
    int base = b * 256;
    for (int r = 0; r < 256; r++) {
        int t = base + r;
        acc += E[t * DIM + j];
        X[t * DIM + j] = acc / (float)(t + 1);
    }
}

// ---------------- fp16 HMMA GEMM, cp.async double-buffered ----------------
// C[row][col] = dot_256(A[row], B[col]); 128x128 CTA tile, K=256 (4 chunks).
// OUTF32=0: half out + per-CTA strip-max keys -> Gmax (scores).
// OUTF32=1: fp32 out, col guard (logits).
// Epilogues stage through smem for fully coalesced global stores.
template <int OUTF32>
__global__ __launch_bounds__(256, 2) void k_hmma(
    const __half* __restrict__ A,
    const __half* __restrict__ B,
    __half* __restrict__ Sout,
    float* __restrict__ Fout,
    u64* __restrict__ Gmax,
    int ncols)
{
    extern __shared__ char smem[];
    u32 aAddr[2] = { smem_u32(smem),         smem_u32(smem + 16384) };
    u32 bAddr[2] = { smem_u32(smem + 32768), smem_u32(smem + 49152) };
    int tid = threadIdx.x;
    int w = tid >> 5, l = tid & 31;
    int wm = w & 3, wn = w >> 2;
    int rowBase = blockIdx.y * 128;
    int colBase = blockIdx.x * 128;

    float acc[2][8][4];
#pragma unroll
    for (int mi = 0; mi < 2; mi++)
#pragma unroll
        for (int ni = 0; ni < 8; ni++)
#pragma unroll
            for (int q = 0; q < 4; q++) acc[mi][ni][q] = 0.f;

    int a_row = wm * 32 + (l & 7) + ((l >> 3) & 1) * 8;   // + mi*16
    int a_kb  = ((l >> 4) * 8) * 2;                        // + ks*32
    int b_row = wn * 64 + (l & 7) + (l >> 4) * 8;          // + nj*16
    int b_kb  = (((l >> 3) & 1) * 8) * 2;                  // + ks*32

    // prologue: async-load chunk 0 into stage 0
#pragma unroll
    for (int g = tid; g < 1024; g += 256) {
        int row = g >> 3, seg = g & 7;
        cp16(aAddr[0] + SWZ128(row * 128 + seg * 16),
             A + (size_t)(rowBase + row) * DIM + seg * 8);
    }
#pragma unroll
    for (int g = tid; g < 1024; g += 256) {
        int row = g >> 3, seg = g & 7;
        cp16(bAddr[0] + SWZ128(row * 128 + seg * 16),
             B + (size_t)(colBase + row) * DIM + seg * 8);
    }
    cp_commit();

#pragma unroll
    for (int i = 0; i < 4; i++) {
        int s = i & 1;
        if (i + 1 < 4) {
            int kc = (i + 1) << 6, sn = (i + 1) & 1;
#pragma unroll
            for (int g = tid; g < 1024; g += 256) {
                int row = g >> 3, seg = g & 7;
                cp16(aAddr[sn] + SWZ128(row * 128 + seg * 16),
                     A + (size_t)(rowBase + row) * DIM + kc + seg * 8);
            }
#pragma unroll
            for (int g = tid; g < 1024; g += 256) {
                int row = g >> 3, seg = g & 7;
                cp16(bAddr[sn] + SWZ128(row * 128 + seg * 16),
                     B + (size_t)(colBase + row) * DIM + kc + seg * 8);
            }
            cp_commit();
            cp_wait<1>();
        } else {
            cp_wait<0>();
        }
        __syncthreads();
#pragma unroll
        for (int ks = 0; ks < 4; ks++) {
            u32 a[2][4];
#pragma unroll
            for (int mi = 0; mi < 2; mi++)
                ldsm4(a[mi], aAddr[s] + SWZ128((a_row + mi * 16) * 128 + a_kb + ks * 32));
            u32 b[4][4];
#pragma unroll
            for (int nj = 0; nj < 4; nj++)
                ldsm4(b[nj], bAddr[s] + SWZ128((b_row + nj * 16) * 128 + b_kb + ks * 32));
#pragma unroll
            for (int mi = 0; mi < 2; mi++)
#pragma unroll
                for (int nj = 0; nj < 4; nj++) {
                    mma_f16(acc[mi][nj * 2],     a[mi], b[nj][0], b[nj][1]);
                    mma_f16(acc[mi][nj * 2 + 1], a[mi], b[nj][2], b[nj][3]);
                }
        }
        __syncthreads();
    }

    // ---- epilogue: stage 128x132 fp32 tile in smem, then coalesced copy-out --
    float* st = (float*)smem;                 // 128*132*4 = 67584 B
    u64* rowmax = (u64*)(smem + 67584);       // 128*8 = 1024 B
    if (!OUTF32 && tid < 128) rowmax[tid] = 0ull;
    __syncthreads();

#pragma unroll
    for (int mi = 0; mi < 2; mi++) {
        int rl0 = wm * 32 + mi * 16 + (l >> 2);
        u64 km0 = 0ull, km8 = 0ull;
#pragma unroll
        for (int ni = 0; ni < 8; ni++) {
            int cl = wn * 64 + ni * 8 + (l & 3) * 2;
            st[rl0 * 132 + cl]           = acc[mi][ni][0];
            st[rl0 * 132 + cl + 1]       = acc[mi][ni][1];
            st[(rl0 + 8) * 132 + cl]     = acc[mi][ni][2];
            st[(rl0 + 8) * 132 + cl + 1] = acc[mi][ni][3];
            if (!OUTF32) {
                // keys from half-rounded values: consistent with stored scores
                int sl = colBase + cl;
                u64 k0 = mk_key(__half2float(__float2half(acc[mi][ni][0])), sl);
                u64 k1 = mk_key(__half2float(__float2half(acc[mi][ni][1])), sl + 1);
                u64 k2 = mk_key(__half2float(__float2half(acc[mi][ni][2])), sl);
                u64 k3 = mk_key(__half2float(__float2half(acc[mi][ni][3])), sl + 1);
                if (k1 > k0) k0 = k1;
                if (k3 > k2) k2 = k3;
                if (k0 > km0) km0 = k0;
                if (k2 > km8) km8 = k2;
            }
        }
        if (!OUTF32) {
            atomicMax(&rowmax[rl0], km0);
            atomicMax(&rowmax[rl0 + 8], km8);
        }
    }
    __syncthreads();

    if (OUTF32) {
        for (int g = tid; g < 16384; g += 256) {
            int row = g >> 7, col = g & 127;
            int c = colBase + col;
            if (c < ncols)
                Fout[(size_t)(rowBase + row) * ncols + c] = st[row * 132 + col];
        }
    } else {
        for (int g = tid; g < 8192; g += 256) {
            int row = g >> 6, cp = g & 63;
            float v0 = st[row * 132 + cp * 2];
            float v1 = st[row * 132 + cp * 2 + 1];
            *(__half2*)&Sout[(size_t)(rowBase + row) * (size_t)ncols + colBase + cp * 2] =
                __floats2half2_rn(v0, v1);
        }
        if (tid < 128)
            Gmax[(size_t)(rowBase + tid) * 512 + blockIdx.x] = rowmax[tid];
    }
}

// ---------------- top-k: Gmax tau -> collect -> exact rescore -> top-64 ------
__global__ __launch_bounds__(256) void k_topk_rescore(
    const __half* __restrict__ S,
    const u64* __restrict__ Gmax,
    const float* __restrict__ E,
    const float* __restrict__ Mm,
    int* __restrict__ Kset
) {
    __shared__ u64 cand[2048];
    __shared__ u64 smax[512];
    __shared__ u64 tmax[256];
    __shared__ float Erow[256];
    __shared__ int cslot[128];
    __shared__ int cnt;
    int tid = threadIdx.x;
    int t = blockIdx.x;
    Erow[tid] = E[t * DIM + tid];
    if (tid == 0) cnt = 0;

    // tau from precomputed 512 strip maxima (each over 128 slots)
    smax[tid]       = Gmax[(size_t)t * 512 + tid];
    smax[tid + 256] = Gmax[(size_t)t * 512 + tid + 256];
    __syncthreads();
    for (int k = 2; k <= 512; k <<= 1) {
        for (int j = k >> 1; j > 0; j >>= 1) {
            for (int e = tid; e < 512; e += 256) {
                int ix = e ^ j;
                if (ix > e) {
                    u64 a = smax[e], b = smax[ix];
                    bool up = ((e & k) == 0);
                    if (up ? (a < b) : (a > b)) { smax[e] = b; smax[ix] = a; }
                }
            }
            __syncthreads();
        }
    }
    u64 tau = smax[127];   // >=128 keys >= tau -> approx top-128 is a subset
    __syncthreads();

    // collection pass: uint4 = 8 halves per load, coalesced
    {
        const uint4* row4 = (const uint4*)(S + (size_t)t * KMEM);
#pragma unroll 4
        for (int i = 0; i < 32; i++) {
            int j4 = tid + (i << 8);
            uint4 v = row4[j4];
            int base = j4 * 8;
            u32 words[4] = { v.x, v.y, v.z, v.w };
#pragma unroll
            for (int q = 0; q < 4; q++) {
                __half2 h = *(__half2*)&words[q];
                u64 k0 = mk_key(__low2float(h), base + 2 * q);
                u64 k1 = mk_key(__high2float(h), base + 2 * q + 1);
                if (k0 >= tau) { int p = atomicAdd(&cnt, 1); if (p < 2048) cand[p] = k0; }
                if (k1 >= tau) { int p = atomicAdd(&cnt, 1); if (p < 2048) cand[p] = k1; }
            }
        }
    }
    __syncthreads();
    int c = cnt; if (c > 2048) c = 2048;
    for (int e = c + tid; e < 2048; e += 256) cand[e] = 0ull;
    __syncthreads();
    for (int k = 2; k <= 2048; k <<= 1) {
        for (int j = k >> 1; j > 0; j >>= 1) {
            for (int e = tid; e < 2048; e += 256) {
                int ix = e ^ j;
                if (ix > e) {
                    u64 a = cand[e], b = cand[ix];
                    bool up = ((e & k) == 0);
                    if (up ? (a < b) : (a > b)) { cand[e] = b; cand[ix] = a; }
                }
            }
            __syncthreads();
        }
    }
    if (tid < 128) cslot[tid] = 65535 - (int)(cand[tid] & 0xFFFFull);
    __syncthreads();

    // exact fp32 rescore of 128 candidates (true top-64 provably inside:
    // fp16 approx sigma ~1.6e-5 vs top64->128 margin ~1.9e-3)
    {
        int w = tid >> 5, l = tid & 31;
        for (int j = 0; j < 16; j++) {
            int ci = w * 16 + j;
            int slot = cslot[ci];
            const float* mrow = &Mm[(size_t)slot * DIM];
            float p = 0.f;
#pragma unroll
            for (int i = 0; i < 8; i++) p = fmaf(Erow[l + 32 * i], mrow[l + 32 * i], p);
#pragma unroll
            for (int o = 16; o > 0; o >>= 1) p += __shfl_xor_sync(0xffffffffu, p, o);
            if (l == 0) tmax[ci] = mk_key(p, slot);
        }
    }
    if (tid >= 128) tmax[tid] = 0ull;
    __syncthreads();

    for (int k = 2; k <= 256; k <<= 1) {
        for (int j = k >> 1; j > 0; j >>= 1) {
            int ix = tid ^ j;
            if (ix > tid) {
                u64 a = tmax[tid], b = tmax[ix];
                bool up = ((tid & k) == 0);
                if (up ? (a < b) : (a > b)) { tmax[tid] = b; tmax[ix] = a; }
            }
            __syncthreads();
        }
    }
    if (tid < 64) Kset[t * 64 + tid] = 65535 - (int)(tmax[tid] & 0xFFFFull);
}

// ---------------- solver: 4 ADMM/mirror-descent steps per token ----------------
#define SLV_FLOATS (64 * 257 + 256 * 17 + 256 + 256 + 64 + 64 + 4 * 64 + 2 + 64)
#define SLV_BYTES  (SLV_FLOATS * 4)

__global__ __launch_bounds__(256) void k_solver(const float* __restrict__ X,
                                                const float* __restrict__ M,
                                                const float* __restrict__ A,
                                                const int* __restrict__ Kidx,
                                                float* __restrict__ Yout,
                                                __half* __restrict__ Yh) {
    extern __shared__ float sm[];
    float* Mg   = sm;                 // [64][257]
    float* band = Mg + 64 * 257;      // [256][17]
    float* Ysm  = band + 256 * 17;    // [256]
    float* vsm  = Ysm + 256;          // [256]
    float* Psm  = vsm + 256;          // [64]
    float* Lsm  = Psm + 64;           // [64]
    float* gp   = Lsm + 64;           // [4][64]
    float* red  = gp + 256;           // [2]
    int*   sidx = (int*)(red + 2);    // [64]

    int tid = threadIdx.x;
    int t = blockIdx.x;
    if (tid < 64) sidx[tid] = Kidx[t * 64 + tid];
    __syncthreads();
    for (int r = 0; r < 64; r++)
        Mg[r * 257 + tid] = M[(size_t)sidx[r] * DIM + tid];
    {
        int j = tid;
#pragma unroll
        for (int o = 0; o < 17; o++) {
            int i = j - 8 + o;
            band[j * 17 + o] = (i >= 0 && i < 256) ? A[j * 256 + i] : 0.f;
        }
    }
    float xr = X[t * DIM + tid];
    if (tid < 64) Psm[tid] = 1.0f / 64.0f;
    __syncthreads();
    {
        float y0 = 0.f;
        for (int k = 0; k < 64; k++) y0 = fmaf(Psm[k], Mg[k * 257 + tid], y0);
        Ysm[tid] = y0;
    }
    float lam = 0.f;
    __syncthreads();

    for (int step = 0; step < 4; step++) {
        float ymp = 0.f;
#pragma unroll 8
        for (int k = 0; k < 64; k++) ymp = fmaf(Psm[k], Mg[k * 257 + tid], ymp);
        float yold = Ysm[tid];
        float r_ = yold - ymp;
        lam = fmaf(RHO_C, r_, lam);
        float yab = 0.f;
#pragma unroll
        for (int o = 0; o < 17; o++) {
            int i = tid - 8 + o;
            if (i >= 0 && i < 256) yab = fmaf(band[tid * 17 + o], Ysm[i], yab);
        }
        float gY = yab - xr + lam + RHO_C * r_;
        float ynew = yold - TAU_C * gY;
        __syncthreads();
        Ysm[tid] = ynew;
        vsm[tid] = RHO_C * (ynew - ymp) + lam;
        __syncthreads();
        {
            int k = tid & 63, part = tid >> 6;
            const float* vv = vsm + part * 64;
            const float* mm = Mg + k * 257 + part * 64;
            float p_ = 0.f;
#pragma unroll 8
            for (int jj = 0; jj < 64; jj++) p_ = fmaf(vv[jj], mm[jj], p_);
            gp[part * 64 + k] = p_;
        }
        __syncthreads();
        if (tid < 64) {
            float gPk = -(gp[tid] + gp[64 + tid] + gp[128 + tid] + gp[192 + tid]);
            Lsm[tid] = logf(Psm[tid] + 1e-20f) - ETA_C * gPk;
        }
        __syncthreads();
        if (tid < 32) {
            float m_ = fmaxf(Lsm[tid], Lsm[tid + 32]);
            for (int o = 16; o > 0; o >>= 1) m_ = fmaxf(m_, __shfl_xor_sync(0xffffffffu, m_, o));
            if (tid == 0) red[0] = m_;
        }
        __syncthreads();
        if (tid < 64) Psm[tid] = expf(Lsm[tid] - red[0]);
        __syncthreads();
        if (tid < 32) {
            float s_ = Psm[tid] + Psm[tid + 32];
            for (int o = 16; o > 0; o >>= 1) s_ += __shfl_xor_sync(0xffffffffu, s_, o);
            if (tid == 0) red[1] = s_;
        }
        __syncthreads();
        if (tid < 64) Psm[tid] = Psm[tid] / red[1];
        __syncthreads();
    }
    float yfin = Ysm[tid];
    Yout[t * DIM + tid] = yfin;
    Yh[t * DIM + tid] = __float2half(yfin);
}

// ---------------- launcher ----------------
extern "C" void kernel_launch(void* const* d_in, const int* in_sizes, int n_in,
                              void* d_out, int out_size) {
    const int*   tokens = (const int*)d_in[0];
    const float* tab    = (const float*)d_in[1];
    const float* M      = (const float*)d_in[2];
    const float* A      = (const float*)d_in[3];
    float* out = (float*)d_out;

    __half *pSh, *pMh, *pEh, *pYh;
    u64* pG;
    float *pE, *pX, *pY, *pB; int* pK;
    cudaGetSymbolAddress((void**)&pSh, g_Sh);
    cudaGetSymbolAddress((void**)&pMh, g_Mh);
    cudaGetSymbolAddress((void**)&pEh, g_Eh);
    cudaGetSymbolAddress((void**)&pYh, g_Yh);
    cudaGetSymbolAddress((void**)&pG, g_Gmax);
    cudaGetSymbolAddress((void**)&pE, g_E);
    cudaGetSymbolAddress((void**)&pX, g_X);
    cudaGetSymbolAddress((void**)&pY, g_Y);
    cudaGetSymbolAddress((void**)&pB, g_bsum);
    cudaGetSymbolAddress((void**)&pK, g_K);

    k_embed<<<N_TOK, 256>>>(tokens, tab, pE, pEh);
    k_colsum<<<8, 256>>>(pE, pB);
    k_cummean<<<8, 256>>>(pE, pB, pX);
    k_cvt_h<<<(KMEM * DIM / 4 + 255) / 256, 256>>>(M, pMh, KMEM * DIM / 4);

    cudaFuncSetAttribute(k_hmma<0>, cudaFuncAttributeMaxDynamicSharedMemorySize, SMEM_BYTES);
    cudaFuncSetAttribute(k_hmma<1>, cudaFuncAttributeMaxDynamicSharedMemorySize, SMEM_BYTES);

    // approx scores: fp16 HMMA + fused strip maxima
    dim3 gs(KMEM / 128, N_TOK / 128);
    k_hmma<0><<<gs, 256, SMEM_BYTES>>>(pEh, pMh, pSh, nullptr, pG, KMEM);

    // tau from Gmax -> collect -> exact fp32 rescore -> exact top-64
    k_topk_rescore<<<N_TOK, 256>>>(pSh, pG, pE, M, pK);

    cudaFuncSetAttribute(k_solver, cudaFuncAttributeMaxDynamicSharedMemorySize, SLV_BYTES);
    k_solver<<<N_TOK, 256, SLV_BYTES>>>(pX, M, A, pK, pY, pYh);

    // logits: single fp16 HMMA (error ~2.9e-4 << 1e-3), staged coalesced stores
    dim3 gl((VOCAB + 127) / 128, N_TOK / 128);
    k_hmma<1><<<gl, 256, SMEM_BYTES>>>(pYh, pMh, nullptr, out, nullptr, VOCAB);
}